// round 1
// baseline (speedup 1.0000x reference)
#include <cuda_runtime.h>
#include <cstdint>
#include <cstddef>

// Problem constants
#define B_  4
#define N_  4096
#define H_  16
#define DH_ 64
#define M_  266
#define D_  1024
#define ROWS_ (B_*H_*N_)        // 262144
#define BN_   (B_*N_)           // 16384

#define DN_    0.3535533906f    // 64^-0.25
#define RATIO_ 0.0613139315f    // 266^-0.5
#define EPS_F  1e-4f
#define EPS_LN 1e-5f

// ------------------------- scratch (device globals) -------------------------
__device__ float g_Q[(size_t)BN_ * D_];
__device__ float g_K[(size_t)BN_ * D_];
__device__ float g_V[(size_t)BN_ * D_];
__device__ float g_qf[(size_t)ROWS_ * M_];
__device__ float g_kf[(size_t)ROWS_ * M_];
__device__ float g_kdiag[ROWS_];
__device__ float g_krowmax[ROWS_];
__device__ float g_kmax[B_ * H_];
__device__ float g_ksum[B_ * H_ * M_];
__device__ float g_ctx[(size_t)B_ * H_ * M_ * DH_];
__device__ float g_dinv[ROWS_];
__device__ float g_attn[(size_t)BN_ * D_];
__device__ float g_out2[(size_t)BN_ * D_];

// ------------------------- SGEMM 128x128x8, 8x8/thread ----------------------
// C[MxN] = A[MxK] * B[KxN], all row-major, M%128==0, N%128==0, K%8==0
__global__ __launch_bounds__(256) void sgemm128(const float* __restrict__ A,
                                                const float* __restrict__ Bm,
                                                float* __restrict__ C,
                                                int Mr, int Nc, int Kd) {
    __shared__ float As[8][128];
    __shared__ float Bs[8][128];

    const int brow = blockIdx.y, bcol = blockIdx.x;
    const int tid = threadIdx.x;
    const int tr = tid >> 4;          // 0..15
    const int tc = tid & 15;          // 0..15

    const int aRow = tid >> 1;        // 0..127
    const int aCol = (tid & 1) * 4;   // 0 or 4
    const int bRow = tid >> 5;        // 0..7
    const int bCol = (tid & 31) * 4;  // 0..124

    const float* Ab = A + (size_t)brow * 128 * Kd;
    const float* Bb = Bm + bcol * 128;

    float acc[8][8];
#pragma unroll
    for (int i = 0; i < 8; i++)
#pragma unroll
        for (int j = 0; j < 8; j++) acc[i][j] = 0.f;

    for (int k0 = 0; k0 < Kd; k0 += 8) {
        float4 a4 = *(const float4*)(Ab + (size_t)aRow * Kd + k0 + aCol);
        As[aCol + 0][aRow] = a4.x;
        As[aCol + 1][aRow] = a4.y;
        As[aCol + 2][aRow] = a4.z;
        As[aCol + 3][aRow] = a4.w;
        float4 b4 = *(const float4*)(Bb + (size_t)(k0 + bRow) * Nc + bCol);
        *(float4*)&Bs[bRow][bCol] = b4;
        __syncthreads();

#pragma unroll
        for (int k = 0; k < 8; k++) {
            float ar[8], br[8];
#pragma unroll
            for (int i = 0; i < 8; i++) ar[i] = As[k][tr * 8 + i];
#pragma unroll
            for (int j = 0; j < 8; j++) br[j] = Bs[k][tc * 8 + j];
#pragma unroll
            for (int i = 0; i < 8; i++)
#pragma unroll
                for (int j = 0; j < 8; j++) acc[i][j] += ar[i] * br[j];
        }
        __syncthreads();
    }

    const int rowBase = brow * 128 + tr * 8;
    const int colBase = bcol * 128 + tc * 8;
#pragma unroll
    for (int i = 0; i < 8; i++) {
        float* cp = C + (size_t)(rowBase + i) * Nc + colBase;
#pragma unroll
        for (int j = 0; j < 8; j++) cp[j] = acc[i][j];
    }
}

// ------------------------- FAVOR+ feature kernels ---------------------------
// MODE 0: query — single pass, per-row stabilizer, writes qf.
// MODE 1: key pass 1 — writes raw xd into kf, diag and row max to side arrays.
template <int MODE>
__global__ __launch_bounds__(128) void feat_kernel(const float* __restrict__ QK,
                                                   const float* __restrict__ proj,
                                                   float* __restrict__ fout,
                                                   float* __restrict__ diag_out,
                                                   float* __restrict__ rowmax_out) {
    const int t = threadIdx.x;
    const int idx = blockIdx.x;        // bh*N + n
    const int bh = idx >> 12;          // N = 4096
    const int n = idx & 4095;
    const int b = bh >> 4, h = bh & 15;

    __shared__ float xs[64];
    __shared__ float smax[128];

    if (t < 64)
        xs[t] = QK[((size_t)(b * N_ + n)) * D_ + h * 64 + t] * DN_;
    __syncthreads();

    float v[3];
    float lmax = -1e30f;
#pragma unroll
    for (int i = 0; i < 3; i++) {
        const int m = t + i * 128;
        float s = 0.f;
        if (m < M_) {
            const float* pr = proj + m * 64;
#pragma unroll
            for (int k = 0; k < 64; k++) s += xs[k] * pr[k];
            lmax = fmaxf(lmax, s);
        }
        v[i] = s;
    }

    // diag = 0.5 * ||xs||^2 (redundant per thread; 64 FMAs)
    float dg = 0.f;
#pragma unroll
    for (int k = 0; k < 64; k++) dg += xs[k] * xs[k];
    dg *= 0.5f;

    smax[t] = lmax;
    __syncthreads();
#pragma unroll
    for (int off = 64; off > 0; off >>= 1) {
        if (t < off) smax[t] = fmaxf(smax[t], smax[t + off]);
        __syncthreads();
    }
    const float rmax = smax[0];

    float* out = fout + (size_t)idx * M_;
    if (MODE == 0) {
#pragma unroll
        for (int i = 0; i < 3; i++) {
            const int m = t + i * 128;
            if (m < M_)
                out[m] = RATIO_ * (expf(v[i] - dg - rmax) + EPS_F);
        }
    } else {
#pragma unroll
        for (int i = 0; i < 3; i++) {
            const int m = t + i * 128;
            if (m < M_) out[m] = v[i];
        }
        if (t == 0) {
            diag_out[idx] = dg;
            rowmax_out[idx] = rmax;
        }
    }
}

__global__ __launch_bounds__(256) void kmax_reduce_kernel(const float* __restrict__ rowmax,
                                                          float* __restrict__ kmax) {
    __shared__ float sm[256];
    const int bh = blockIdx.x;
    float v = -1e30f;
    for (int i = threadIdx.x; i < N_; i += 256)
        v = fmaxf(v, rowmax[bh * N_ + i]);
    sm[threadIdx.x] = v;
    __syncthreads();
#pragma unroll
    for (int off = 128; off > 0; off >>= 1) {
        if (threadIdx.x < off) sm[threadIdx.x] = fmaxf(sm[threadIdx.x], sm[threadIdx.x + off]);
        __syncthreads();
    }
    if (threadIdx.x == 0) kmax[bh] = sm[0];
}

__global__ __launch_bounds__(128) void kfeat2_kernel(float* __restrict__ kf,
                                                     const float* __restrict__ kdiag,
                                                     const float* __restrict__ kmax) {
    const int idx = blockIdx.x;
    const int bh = idx >> 12;
    const float sub = kdiag[idx] + kmax[bh];
    float* row = kf + (size_t)idx * M_;
    for (int m = threadIdx.x; m < M_; m += 128)
        row[m] = RATIO_ * (expf(row[m] - sub) + EPS_F);
}

// ------------------------- linear attention ---------------------------------
__global__ __launch_bounds__(288) void ksum_kernel(const float* __restrict__ kf,
                                                   float* __restrict__ ksum) {
    const int bh = blockIdx.x;
    const int m = threadIdx.x;
    if (m >= M_) return;
    float s = 0.f;
    const float* base = kf + (size_t)bh * N_ * M_ + m;
    for (int n = 0; n < N_; n++) s += base[(size_t)n * M_];
    ksum[bh * M_ + m] = s;
}

// ctx[bh][m][d] = sum_n kf[bh][n][m] * V[b][n][h*64+d]
__global__ __launch_bounds__(256) void ctx_kernel(const float* __restrict__ kf,
                                                  const float* __restrict__ V,
                                                  float* __restrict__ ctx) {
    __shared__ float Ks[32][32];
    __shared__ float Vs[32][64];

    const int bh = blockIdx.y;
    const int b = bh >> 4, h = bh & 15;
    const int m0 = blockIdx.x * 32;
    const int t = threadIdx.x;
    const int d = t & 63;
    const int mb = (t >> 6) * 8;

    float acc[8];
#pragma unroll
    for (int j = 0; j < 8; j++) acc[j] = 0.f;

    for (int n0 = 0; n0 < N_; n0 += 32) {
#pragma unroll
        for (int q = 0; q < 4; q++) {
            const int idx = t + q * 256;
            const int i = idx >> 5, j = idx & 31;
            const int m = m0 + j;
            Ks[i][j] = (m < M_) ? kf[((size_t)(bh * N_ + n0 + i)) * M_ + m] : 0.f;
        }
#pragma unroll
        for (int q = 0; q < 8; q++) {
            const int idx = t + q * 256;
            const int i = idx >> 6, dd = idx & 63;
            Vs[i][dd] = V[((size_t)(b * N_ + n0 + i)) * D_ + h * 64 + dd];
        }
        __syncthreads();
#pragma unroll 8
        for (int i = 0; i < 32; i++) {
            const float vv = Vs[i][d];
#pragma unroll
            for (int j = 0; j < 8; j++) acc[j] += Ks[i][mb + j] * vv;
        }
        __syncthreads();
    }

#pragma unroll
    for (int j = 0; j < 8; j++) {
        const int m = m0 + mb + j;
        if (m < M_) ctx[((size_t)bh * M_ + m) * 64 + d] = acc[j];
    }
}

__global__ __launch_bounds__(256) void dinv_kernel(const float* __restrict__ qf,
                                                   const float* __restrict__ ksum,
                                                   float* __restrict__ dinv) {
    const int row = blockIdx.x * 8 + (threadIdx.x >> 5);
    const int lane = threadIdx.x & 31;
    const int bh = row >> 12;
    float s = 0.f;
    const float* qr = qf + (size_t)row * M_;
    const float* ks = ksum + bh * M_;
    for (int m = lane; m < M_; m += 32) s += qr[m] * ks[m];
#pragma unroll
    for (int off = 16; off > 0; off >>= 1) s += __shfl_xor_sync(0xffffffff, s, off);
    if (lane == 0) dinv[row] = 1.f / s;
}

// out[b][n][h*64+d] = dinv * sum_m qf[bh][n][m] * ctx[bh][m][d]
__global__ __launch_bounds__(256) void attn_out_kernel(const float* __restrict__ qf,
                                                       const float* __restrict__ ctx,
                                                       const float* __restrict__ dinv,
                                                       float* __restrict__ out) {
    __shared__ float Cs[64][64];
    __shared__ float Qs[16][64];

    const int bh = blockIdx.y;
    const int b = bh >> 4, h = bh & 15;
    const int n0 = blockIdx.x * 16;
    const int t = threadIdx.x;
    const int d = t & 63;
    const int rg = (t >> 6) * 4;

    float acc[4] = {0.f, 0.f, 0.f, 0.f};

    for (int c = 0; c < 5; c++) {
        const int m0 = c * 64;
        const int mw = (M_ - m0 < 64) ? (M_ - m0) : 64;
#pragma unroll
        for (int q = 0; q < 16; q++) {
            const int idx = t + q * 256;
            const int mm = idx >> 6, dd = idx & 63;
            Cs[mm][dd] = (mm < mw) ? ctx[((size_t)bh * M_ + m0 + mm) * 64 + dd] : 0.f;
        }
#pragma unroll
        for (int q = 0; q < 4; q++) {
            const int idx = t + q * 256;
            const int r = idx >> 6, mm = idx & 63;
            Qs[r][mm] = (mm < mw) ? qf[((size_t)(bh * N_ + n0 + r)) * M_ + m0 + mm] : 0.f;
        }
        __syncthreads();
#pragma unroll 8
        for (int mm = 0; mm < 64; mm++) {
            const float cv = Cs[mm][d];
#pragma unroll
            for (int ii = 0; ii < 4; ii++) acc[ii] += Qs[rg + ii][mm] * cv;
        }
        __syncthreads();
    }

#pragma unroll
    for (int ii = 0; ii < 4; ii++) {
        const int n = n0 + rg + ii;
        out[((size_t)(b * N_ + n)) * D_ + h * 64 + d] = acc[ii] * dinv[bh * N_ + n];
    }
}

// ------------------------- residual + LayerNorm -----------------------------
__global__ __launch_bounds__(256) void ln_kernel(const float* __restrict__ x,
                                                 const float* __restrict__ o2,
                                                 const float* __restrict__ bo,
                                                 const float* __restrict__ gamma,
                                                 const float* __restrict__ beta,
                                                 float* __restrict__ out) {
    __shared__ float ss[256];
    __shared__ float sq[256];
    const int row = blockIdx.x;
    const int t = threadIdx.x;
    const size_t base = (size_t)row * D_;

    float yv[4];
    float s = 0.f, q = 0.f;
#pragma unroll
    for (int i = 0; i < 4; i++) {
        const int c = t + i * 256;
        const float v = x[base + c] + o2[base + c] + bo[c];
        yv[i] = v;
        s += v;
        q += v * v;
    }
    ss[t] = s;
    sq[t] = q;
    __syncthreads();
#pragma unroll
    for (int off = 128; off > 0; off >>= 1) {
        if (t < off) { ss[t] += ss[t + off]; sq[t] += sq[t + off]; }
        __syncthreads();
    }
    const float mu = ss[0] * (1.f / (float)D_);
    const float var = sq[0] * (1.f / (float)D_) - mu * mu;
    const float rstd = rsqrtf(var + EPS_LN);
#pragma unroll
    for (int i = 0; i < 4; i++) {
        const int c = t + i * 256;
        out[base + c] = (yv[i] - mu) * rstd * gamma[c] + beta[c];
    }
}

// ------------------------- launch --------------------------------------------
extern "C" void kernel_launch(void* const* d_in, const int* in_sizes, int n_in,
                              void* d_out, int out_size) {
    const float* x     = (const float*)d_in[0];
    const float* Wq    = (const float*)d_in[1];
    const float* Wk    = (const float*)d_in[2];
    const float* Wv    = (const float*)d_in[3];
    const float* Wo    = (const float*)d_in[4];
    const float* bo    = (const float*)d_in[5];
    const float* proj  = (const float*)d_in[6];
    const float* gamma = (const float*)d_in[7];
    const float* beta  = (const float*)d_in[8];
    float* out = (float*)d_out;

    float *pQ, *pK, *pV, *pqf, *pkf, *pkd, *prm, *pkm, *pks, *pctx, *pdi, *pat, *po2;
    cudaGetSymbolAddress((void**)&pQ,   g_Q);
    cudaGetSymbolAddress((void**)&pK,   g_K);
    cudaGetSymbolAddress((void**)&pV,   g_V);
    cudaGetSymbolAddress((void**)&pqf,  g_qf);
    cudaGetSymbolAddress((void**)&pkf,  g_kf);
    cudaGetSymbolAddress((void**)&pkd,  g_kdiag);
    cudaGetSymbolAddress((void**)&prm,  g_krowmax);
    cudaGetSymbolAddress((void**)&pkm,  g_kmax);
    cudaGetSymbolAddress((void**)&pks,  g_ksum);
    cudaGetSymbolAddress((void**)&pctx, g_ctx);
    cudaGetSymbolAddress((void**)&pdi,  g_dinv);
    cudaGetSymbolAddress((void**)&pat,  g_attn);
    cudaGetSymbolAddress((void**)&po2,  g_out2);

    dim3 gemmGrid(D_ / 128, BN_ / 128);  // (8, 128)

    // 1. QKV projections
    sgemm128<<<gemmGrid, 256>>>(x, Wq, pQ, BN_, D_, D_);
    sgemm128<<<gemmGrid, 256>>>(x, Wk, pK, BN_, D_, D_);
    sgemm128<<<gemmGrid, 256>>>(x, Wv, pV, BN_, D_, D_);

    // 2. FAVOR+ features
    feat_kernel<0><<<ROWS_, 128>>>(pQ, proj, pqf, nullptr, nullptr);
    feat_kernel<1><<<ROWS_, 128>>>(pK, proj, pkf, pkd, prm);
    kmax_reduce_kernel<<<B_ * H_, 256>>>(prm, pkm);
    kfeat2_kernel<<<ROWS_, 128>>>(pkf, pkd, pkm);

    // 3. Linear attention
    ksum_kernel<<<B_ * H_, 288>>>(pkf, pks);
    ctx_kernel<<<dim3(9, B_ * H_), 256>>>(pkf, pV, pctx);
    dinv_kernel<<<ROWS_ / 8, 256>>>(pqf, pks, pdi);
    attn_out_kernel<<<dim3(N_ / 16, B_ * H_), 256>>>(pqf, pctx, pdi, pat);

    // 4. Output projection + residual + LayerNorm
    sgemm128<<<gemmGrid, 256>>>(pat, Wo, po2, BN_, D_, D_);
    ln_kernel<<<BN_, 256>>>(x, po2, bo, gamma, beta, out);
}

// round 3
// speedup vs baseline: 1.0632x; 1.0632x over previous
#include <cuda_runtime.h>
#include <cuda_bf16.h>
#include <cstdint>
#include <cstddef>

// Problem constants
#define B_  4
#define N_  4096
#define H_  16
#define DH_ 64
#define M_  266
#define D_  1024
#define ROWS_ (B_*H_*N_)        // 262144
#define BN_   (B_*N_)           // 16384

#define DN_    0.3535533906f    // 64^-0.25
#define RATIO_ 0.0613139315f    // 266^-0.5
#define EPS_F  1e-4f
#define EPS_LN 1e-5f

// ------------------------- scratch (device globals) -------------------------
__device__ float g_Q[(size_t)BN_ * D_];
__device__ float g_K[(size_t)BN_ * D_];
__device__ float g_V[(size_t)BN_ * D_];
__device__ float g_qf[(size_t)ROWS_ * M_];
__device__ float g_kf[(size_t)ROWS_ * M_];
__device__ float g_kdiag[ROWS_];
__device__ float g_krowmax[ROWS_];
__device__ float g_kmax[B_ * H_];
__device__ float g_ksum[B_ * H_ * M_];
__device__ float g_ctx[(size_t)B_ * H_ * M_ * DH_];
__device__ float g_dinv[ROWS_];
__device__ float g_out2[(size_t)BN_ * D_];

// split operands (bf16 hi/lo)
__device__ __nv_bfloat16 g_xh[(size_t)BN_ * D_];
__device__ __nv_bfloat16 g_xl[(size_t)BN_ * D_];
__device__ __nv_bfloat16 g_ah[(size_t)BN_ * D_];
__device__ __nv_bfloat16 g_al[(size_t)BN_ * D_];
__device__ __nv_bfloat16 g_Wth[4][(size_t)D_ * D_];  // W^T hi: [n][k]
__device__ __nv_bfloat16 g_Wtl[4][(size_t)D_ * D_];  // W^T lo

// ------------------------- helpers ------------------------------------------
__device__ __forceinline__ uint32_t smem_u32(const void* p) {
    uint32_t a;
    asm("{ .reg .u64 t; cvta.to.shared.u64 t, %1; cvt.u32.u64 %0, t; }" : "=r"(a) : "l"(p));
    return a;
}

__device__ __forceinline__ void ldm_x4(uint32_t addr, uint32_t& r0, uint32_t& r1,
                                       uint32_t& r2, uint32_t& r3) {
    asm volatile("ldmatrix.sync.aligned.m8n8.x4.shared.b16 {%0,%1,%2,%3}, [%4];"
                 : "=r"(r0), "=r"(r1), "=r"(r2), "=r"(r3) : "r"(addr));
}

__device__ __forceinline__ void mma_bf16(float* c, const uint32_t* a, const uint32_t* b) {
    asm volatile(
        "mma.sync.aligned.m16n8k16.row.col.f32.bf16.bf16.f32 "
        "{%0,%1,%2,%3}, {%4,%5,%6,%7}, {%8,%9}, {%0,%1,%2,%3};"
        : "+f"(c[0]), "+f"(c[1]), "+f"(c[2]), "+f"(c[3])
        : "r"(a[0]), "r"(a[1]), "r"(a[2]), "r"(a[3]), "r"(b[0]), "r"(b[1]));
}

// ------------------------- split / transpose kernels ------------------------
__global__ __launch_bounds__(256) void split_x_kernel(const float* __restrict__ x,
                                                      __nv_bfloat16* __restrict__ xh,
                                                      __nv_bfloat16* __restrict__ xl) {
    const size_t i = ((size_t)blockIdx.x * 256 + threadIdx.x) * 4;
    float4 v = *(const float4*)(x + i);
    float a[4] = {v.x, v.y, v.z, v.w};
#pragma unroll
    for (int j = 0; j < 4; j++) {
        __nv_bfloat16 h = __float2bfloat16(a[j]);
        xh[i + j] = h;
        xl[i + j] = __float2bfloat16(a[j] - __bfloat162float(h));
    }
}

// transpose + split: Th[n][k] = bf16(W[k][n]); Tl = residual
__global__ __launch_bounds__(1024) void splitT_W_kernel(const float* __restrict__ W,
                                                        __nv_bfloat16* __restrict__ Th,
                                                        __nv_bfloat16* __restrict__ Tl) {
    __shared__ float tile[32][33];
    const int n = blockIdx.x * 32 + threadIdx.x;
    const int k = blockIdx.y * 32 + threadIdx.y;
    tile[threadIdx.y][threadIdx.x] = W[(size_t)k * D_ + n];
    __syncthreads();
    const float v = tile[threadIdx.x][threadIdx.y];
    const int on = blockIdx.x * 32 + threadIdx.y;
    const int ok = blockIdx.y * 32 + threadIdx.x;
    __nv_bfloat16 h = __float2bfloat16(v);
    Th[(size_t)on * D_ + ok] = h;
    Tl[(size_t)on * D_ + ok] = __float2bfloat16(v - __bfloat162float(h));
}

// ------------------------- mma.sync bf16-split GEMM -------------------------
// C[16384 x 1024] = (Ah+Al) * (Bh+Bl)^T; B stored [N=1024][K=1024].
// CTA tile 128x128, warp tile 64x32 (2x4 warps), KC=32 double-buffered.
#define KC    32
#define PITCH 80                    // bytes per smem row (64 data + 16 pad)
#define OPB   (128 * PITCH)         // 10240 bytes per operand tile
#define STAGEB (4 * OPB)            // Ah, Al, Bh, Bl
#define GSMEM (2 * STAGEB)          // 81920

__global__ __launch_bounds__(256, 1) void gemm_bf16x3(
    const __nv_bfloat16* __restrict__ Ah, const __nv_bfloat16* __restrict__ Al,
    const __nv_bfloat16* __restrict__ Bh, const __nv_bfloat16* __restrict__ Bl,
    float* __restrict__ C) {
    extern __shared__ char smem[];
    const uint32_t sb = smem_u32(smem);
    const int tid = threadIdx.x;
    const int wid = tid >> 5;
    const int lid = tid & 31;
    const int warp_m = wid & 1;       // 0..1
    const int warp_n = wid >> 1;      // 0..3
    const int row0 = blockIdx.y * 128;
    const int col0 = blockIdx.x * 128;

    const __nv_bfloat16* gA[2] = {Ah + (size_t)row0 * D_, Al + (size_t)row0 * D_};
    const __nv_bfloat16* gB[2] = {Bh + (size_t)col0 * D_, Bl + (size_t)col0 * D_};

    // global-load addressing: 512 uint4 per operand tile; 2 per thread
    const int r0i = (tid * 2) >> 2;          // row of first uint4
    const int s0i = (tid * 2) & 3;           // segment (8 bf16 each)
    const int r1i = (tid * 2 + 1) >> 2;
    const int s1i = (tid * 2 + 1) & 3;

    // ldmatrix per-lane base offsets
    const uint32_t a_base = (uint32_t)((warp_m * 64 + (lid & 15)) * PITCH + (lid >> 4) * 16);
    const uint32_t b_base = (uint32_t)((warp_n * 32 + ((lid >> 4) * 8) + (lid & 7)) * PITCH +
                                       ((lid >> 3) & 1) * 16);

    float acc[4][4][4];
#pragma unroll
    for (int mi = 0; mi < 4; mi++)
#pragma unroll
        for (int ni = 0; ni < 4; ni++)
#pragma unroll
            for (int q = 0; q < 4; q++) acc[mi][ni][q] = 0.f;

    uint4 pf[4][2];
    // prefetch chunk 0
#pragma unroll
    for (int o = 0; o < 2; o++) {
        pf[o][0]     = *(const uint4*)(gA[o] + (size_t)r0i * D_ + s0i * 8);
        pf[o][1]     = *(const uint4*)(gA[o] + (size_t)r1i * D_ + s1i * 8);
        pf[o + 2][0] = *(const uint4*)(gB[o] + (size_t)r0i * D_ + s0i * 8);
        pf[o + 2][1] = *(const uint4*)(gB[o] + (size_t)r1i * D_ + s1i * 8);
    }

    for (int c = 0; c < D_ / KC; c++) {
        const uint32_t stage = (c & 1) * STAGEB;
        // store prefetched chunk to smem
#pragma unroll
        for (int o = 0; o < 4; o++) {
            *(uint4*)(smem + stage + o * OPB + r0i * PITCH + s0i * 16) = pf[o][0];
            *(uint4*)(smem + stage + o * OPB + r1i * PITCH + s1i * 16) = pf[o][1];
        }
        __syncthreads();

        // prefetch next chunk (overlaps with compute below)
        if (c + 1 < D_ / KC) {
            const int k0 = (c + 1) * KC;
#pragma unroll
            for (int o = 0; o < 2; o++) {
                pf[o][0]     = *(const uint4*)(gA[o] + (size_t)r0i * D_ + k0 + s0i * 8);
                pf[o][1]     = *(const uint4*)(gA[o] + (size_t)r1i * D_ + k0 + s1i * 8);
                pf[o + 2][0] = *(const uint4*)(gB[o] + (size_t)r0i * D_ + k0 + s0i * 8);
                pf[o + 2][1] = *(const uint4*)(gB[o] + (size_t)r1i * D_ + k0 + s1i * 8);
            }
        }

        const uint32_t sAh = sb + stage;
        const uint32_t sAl = sb + stage + OPB;
        const uint32_t sBh = sb + stage + 2 * OPB;
        const uint32_t sBl = sb + stage + 3 * OPB;

#pragma unroll
        for (int ks = 0; ks < 2; ks++) {
            const uint32_t kb = ks * 32;  // 16 bf16 = 32 bytes
            uint32_t ah[4][4], al[4][4], bh[4][2], bl[4][2];
#pragma unroll
            for (int mi = 0; mi < 4; mi++) {
                const uint32_t ao = a_base + mi * 16 * PITCH + kb;
                ldm_x4(sAh + ao, ah[mi][0], ah[mi][1], ah[mi][2], ah[mi][3]);
                ldm_x4(sAl + ao, al[mi][0], al[mi][1], al[mi][2], al[mi][3]);
            }
#pragma unroll
            for (int p = 0; p < 2; p++) {
                const uint32_t bo = b_base + p * 16 * PITCH + kb;
                ldm_x4(sBh + bo, bh[2 * p][0], bh[2 * p][1], bh[2 * p + 1][0], bh[2 * p + 1][1]);
                ldm_x4(sBl + bo, bl[2 * p][0], bl[2 * p][1], bl[2 * p + 1][0], bl[2 * p + 1][1]);
            }
#pragma unroll
            for (int mi = 0; mi < 4; mi++)
#pragma unroll
                for (int ni = 0; ni < 4; ni++) {
                    mma_bf16(acc[mi][ni], ah[mi], bh[ni]);
                    mma_bf16(acc[mi][ni], ah[mi], bl[ni]);
                    mma_bf16(acc[mi][ni], al[mi], bh[ni]);
                }
        }
        __syncthreads();
    }

    // epilogue
    const int g = lid >> 2, tg = lid & 3;
#pragma unroll
    for (int mi = 0; mi < 4; mi++) {
#pragma unroll
        for (int ni = 0; ni < 4; ni++) {
            const int row = row0 + warp_m * 64 + mi * 16 + g;
            const int col = col0 + warp_n * 32 + ni * 8 + tg * 2;
            float2 v0 = {acc[mi][ni][0], acc[mi][ni][1]};
            float2 v1 = {acc[mi][ni][2], acc[mi][ni][3]};
            *(float2*)(C + (size_t)row * D_ + col) = v0;
            *(float2*)(C + (size_t)(row + 8) * D_ + col) = v1;
        }
    }
}

// ------------------------- FAVOR+ feature kernels ---------------------------
template <int MODE>
__global__ __launch_bounds__(128) void feat_kernel(const float* __restrict__ QK,
                                                   const float* __restrict__ proj,
                                                   float* __restrict__ fout,
                                                   float* __restrict__ diag_out,
                                                   float* __restrict__ rowmax_out) {
    const int t = threadIdx.x;
    const int idx = blockIdx.x;        // bh*N + n
    const int bh = idx >> 12;
    const int n = idx & 4095;
    const int b = bh >> 4, h = bh & 15;

    __shared__ float xs[64];
    __shared__ float smax[128];

    if (t < 64)
        xs[t] = QK[((size_t)(b * N_ + n)) * D_ + h * 64 + t] * DN_;
    __syncthreads();

    float v[3];
    float lmax = -1e30f;
#pragma unroll
    for (int i = 0; i < 3; i++) {
        const int m = t + i * 128;
        float s = 0.f;
        if (m < M_) {
            const float* pr = proj + m * 64;
#pragma unroll
            for (int k = 0; k < 64; k++) s += xs[k] * pr[k];
            lmax = fmaxf(lmax, s);
        }
        v[i] = s;
    }

    float dg = 0.f;
#pragma unroll
    for (int k = 0; k < 64; k++) dg += xs[k] * xs[k];
    dg *= 0.5f;

    smax[t] = lmax;
    __syncthreads();
#pragma unroll
    for (int off = 64; off > 0; off >>= 1) {
        if (t < off) smax[t] = fmaxf(smax[t], smax[t + off]);
        __syncthreads();
    }
    const float rmax = smax[0];

    float* out = fout + (size_t)idx * M_;
    if (MODE == 0) {
#pragma unroll
        for (int i = 0; i < 3; i++) {
            const int m = t + i * 128;
            if (m < M_)
                out[m] = RATIO_ * (expf(v[i] - dg - rmax) + EPS_F);
        }
    } else {
#pragma unroll
        for (int i = 0; i < 3; i++) {
            const int m = t + i * 128;
            if (m < M_) out[m] = v[i];
        }
        if (t == 0) {
            diag_out[idx] = dg;
            rowmax_out[idx] = rmax;
        }
    }
}

__global__ __launch_bounds__(256) void kmax_reduce_kernel(const float* __restrict__ rowmax,
                                                          float* __restrict__ kmax) {
    __shared__ float sm[256];
    const int bh = blockIdx.x;
    float v = -1e30f;
    for (int i = threadIdx.x; i < N_; i += 256)
        v = fmaxf(v, rowmax[bh * N_ + i]);
    sm[threadIdx.x] = v;
    __syncthreads();
#pragma unroll
    for (int off = 128; off > 0; off >>= 1) {
        if (threadIdx.x < off) sm[threadIdx.x] = fmaxf(sm[threadIdx.x], sm[threadIdx.x + off]);
        __syncthreads();
    }
    if (threadIdx.x == 0) kmax[bh] = sm[0];
}

__global__ __launch_bounds__(128) void kfeat2_kernel(float* __restrict__ kf,
                                                     const float* __restrict__ kdiag,
                                                     const float* __restrict__ kmax) {
    const int idx = blockIdx.x;
    const int bh = idx >> 12;
    const float sub = kdiag[idx] + kmax[bh];
    float* row = kf + (size_t)idx * M_;
    for (int m = threadIdx.x; m < M_; m += 128)
        row[m] = RATIO_ * (expf(row[m] - sub) + EPS_F);
}

// ------------------------- linear attention ---------------------------------
__global__ __launch_bounds__(288) void ksum_kernel(const float* __restrict__ kf,
                                                   float* __restrict__ ksum) {
    const int bh = blockIdx.x;
    const int m = threadIdx.x;
    if (m >= M_) return;
    float s = 0.f;
    const float* base = kf + (size_t)bh * N_ * M_ + m;
    for (int n = 0; n < N_; n++) s += base[(size_t)n * M_];
    ksum[bh * M_ + m] = s;
}

__global__ __launch_bounds__(256) void ctx_kernel(const float* __restrict__ kf,
                                                  const float* __restrict__ V,
                                                  float* __restrict__ ctx) {
    __shared__ float Ks[32][32];
    __shared__ float Vs[32][64];

    const int bh = blockIdx.y;
    const int b = bh >> 4, h = bh & 15;
    const int m0 = blockIdx.x * 32;
    const int t = threadIdx.x;
    const int d = t & 63;
    const int mb = (t >> 6) * 8;

    float acc[8];
#pragma unroll
    for (int j = 0; j < 8; j++) acc[j] = 0.f;

    for (int n0 = 0; n0 < N_; n0 += 32) {
#pragma unroll
        for (int q = 0; q < 4; q++) {
            const int idx = t + q * 256;
            const int i = idx >> 5, j = idx & 31;
            const int m = m0 + j;
            Ks[i][j] = (m < M_) ? kf[((size_t)(bh * N_ + n0 + i)) * M_ + m] : 0.f;
        }
#pragma unroll
        for (int q = 0; q < 8; q++) {
            const int idx = t + q * 256;
            const int i = idx >> 6, dd = idx & 63;
            Vs[i][dd] = V[((size_t)(b * N_ + n0 + i)) * D_ + h * 64 + dd];
        }
        __syncthreads();
#pragma unroll 8
        for (int i = 0; i < 32; i++) {
            const float vv = Vs[i][d];
#pragma unroll
            for (int j = 0; j < 8; j++) acc[j] += Ks[i][mb + j] * vv;
        }
        __syncthreads();
    }

#pragma unroll
    for (int j = 0; j < 8; j++) {
        const int m = m0 + mb + j;
        if (m < M_) ctx[((size_t)bh * M_ + m) * 64 + d] = acc[j];
    }
}

__global__ __launch_bounds__(256) void dinv_kernel(const float* __restrict__ qf,
                                                   const float* __restrict__ ksum,
                                                   float* __restrict__ dinv) {
    const int row = blockIdx.x * 8 + (threadIdx.x >> 5);
    const int lane = threadIdx.x & 31;
    const int bh = row >> 12;
    float s = 0.f;
    const float* qr = qf + (size_t)row * M_;
    const float* ks = ksum + bh * M_;
    for (int m = lane; m < M_; m += 32) s += qr[m] * ks[m];
#pragma unroll
    for (int off = 16; off > 0; off >>= 1) s += __shfl_xor_sync(0xffffffff, s, off);
    if (lane == 0) dinv[row] = 1.f / s;
}

// out -> split bf16 (for Wo mma GEMM)
__global__ __launch_bounds__(256) void attn_out_kernel(const float* __restrict__ qf,
                                                       const float* __restrict__ ctx,
                                                       const float* __restrict__ dinv,
                                                       __nv_bfloat16* __restrict__ ah,
                                                       __nv_bfloat16* __restrict__ al) {
    __shared__ float Cs[64][64];
    __shared__ float Qs[16][64];

    const int bh = blockIdx.y;
    const int b = bh >> 4, h = bh & 15;
    const int n0 = blockIdx.x * 16;
    const int t = threadIdx.x;
    const int d = t & 63;
    const int rg = (t >> 6) * 4;

    float acc[4] = {0.f, 0.f, 0.f, 0.f};

    for (int c = 0; c < 5; c++) {
        const int m0 = c * 64;
        const int mw = (M_ - m0 < 64) ? (M_ - m0) : 64;
#pragma unroll
        for (int q = 0; q < 16; q++) {
            const int idx = t + q * 256;
            const int mm = idx >> 6, dd = idx & 63;
            Cs[mm][dd] = (mm < mw) ? ctx[((size_t)bh * M_ + m0 + mm) * 64 + dd] : 0.f;
        }
#pragma unroll
        for (int q = 0; q < 4; q++) {
            const int idx = t + q * 256;
            const int r = idx >> 6, mm = idx & 63;
            Qs[r][mm] = (mm < mw) ? qf[((size_t)(bh * N_ + n0 + r)) * M_ + m0 + mm] : 0.f;
        }
        __syncthreads();
#pragma unroll 8
        for (int mm = 0; mm < 64; mm++) {
            const float cv = Cs[mm][d];
#pragma unroll
            for (int ii = 0; ii < 4; ii++) acc[ii] += Qs[rg + ii][mm] * cv;
        }
        __syncthreads();
    }

#pragma unroll
    for (int ii = 0; ii < 4; ii++) {
        const int n = n0 + rg + ii;
        const float v = acc[ii] * dinv[bh * N_ + n];
        const size_t o = ((size_t)(b * N_ + n)) * D_ + h * 64 + d;
        __nv_bfloat16 hv = __float2bfloat16(v);
        ah[o] = hv;
        al[o] = __float2bfloat16(v - __bfloat162float(hv));
    }
}

// ------------------------- residual + LayerNorm -----------------------------
__global__ __launch_bounds__(256) void ln_kernel(const float* __restrict__ x,
                                                 const float* __restrict__ o2,
                                                 const float* __restrict__ bo,
                                                 const float* __restrict__ gamma,
                                                 const float* __restrict__ beta,
                                                 float* __restrict__ out) {
    __shared__ float ss[256];
    __shared__ float sq[256];
    const int row = blockIdx.x;
    const int t = threadIdx.x;
    const size_t base = (size_t)row * D_;

    float yv[4];
    float s = 0.f, q = 0.f;
#pragma unroll
    for (int i = 0; i < 4; i++) {
        const int c = t + i * 256;
        const float v = x[base + c] + o2[base + c] + bo[c];
        yv[i] = v;
        s += v;
        q += v * v;
    }
    ss[t] = s;
    sq[t] = q;
    __syncthreads();
#pragma unroll
    for (int off = 128; off > 0; off >>= 1) {
        if (t < off) { ss[t] += ss[t + off]; sq[t] += sq[t + off]; }
        __syncthreads();
    }
    const float mu = ss[0] * (1.f / (float)D_);
    const float var = sq[0] * (1.f / (float)D_) - mu * mu;
    const float rstd = rsqrtf(var + EPS_LN);
#pragma unroll
    for (int i = 0; i < 4; i++) {
        const int c = t + i * 256;
        out[base + c] = (yv[i] - mu) * rstd * gamma[c] + beta[c];
    }
}

// ------------------------- launch --------------------------------------------
extern "C" void kernel_launch(void* const* d_in, const int* in_sizes, int n_in,
                              void* d_out, int out_size) {
    const float* x     = (const float*)d_in[0];
    const float* Wq    = (const float*)d_in[1];
    const float* Wk    = (const float*)d_in[2];
    const float* Wv    = (const float*)d_in[3];
    const float* Wo    = (const float*)d_in[4];
    const float* bo    = (const float*)d_in[5];
    const float* proj  = (const float*)d_in[6];
    const float* gamma = (const float*)d_in[7];
    const float* beta  = (const float*)d_in[8];
    float* out = (float*)d_out;

    float *pQ, *pK, *pV, *pqf, *pkf, *pkd, *prm, *pkm, *pks, *pctx, *pdi, *po2;
    __nv_bfloat16 *pxh, *pxl, *pah, *pal, *pWth, *pWtl;
    cudaGetSymbolAddress((void**)&pQ,   g_Q);
    cudaGetSymbolAddress((void**)&pK,   g_K);
    cudaGetSymbolAddress((void**)&pV,   g_V);
    cudaGetSymbolAddress((void**)&pqf,  g_qf);
    cudaGetSymbolAddress((void**)&pkf,  g_kf);
    cudaGetSymbolAddress((void**)&pkd,  g_kdiag);
    cudaGetSymbolAddress((void**)&prm,  g_krowmax);
    cudaGetSymbolAddress((void**)&pkm,  g_kmax);
    cudaGetSymbolAddress((void**)&pks,  g_ksum);
    cudaGetSymbolAddress((void**)&pctx, g_ctx);
    cudaGetSymbolAddress((void**)&pdi,  g_dinv);
    cudaGetSymbolAddress((void**)&po2,  g_out2);
    cudaGetSymbolAddress((void**)&pxh,  g_xh);
    cudaGetSymbolAddress((void**)&pxl,  g_xl);
    cudaGetSymbolAddress((void**)&pah,  g_ah);
    cudaGetSymbolAddress((void**)&pal,  g_al);
    cudaGetSymbolAddress((void**)&pWth, g_Wth);
    cudaGetSymbolAddress((void**)&pWtl, g_Wtl);

    cudaFuncSetAttribute(gemm_bf16x3, cudaFuncAttributeMaxDynamicSharedMemorySize, GSMEM);

    const size_t WSZ = (size_t)D_ * D_;

    // 0. operand prep
    split_x_kernel<<<BN_ * D_ / (256 * 4), 256>>>(x, pxh, pxl);
    splitT_W_kernel<<<dim3(32, 32), dim3(32, 32)>>>(Wq, pWth + 0 * WSZ, pWtl + 0 * WSZ);
    splitT_W_kernel<<<dim3(32, 32), dim3(32, 32)>>>(Wk, pWth + 1 * WSZ, pWtl + 1 * WSZ);
    splitT_W_kernel<<<dim3(32, 32), dim3(32, 32)>>>(Wv, pWth + 2 * WSZ, pWtl + 2 * WSZ);
    splitT_W_kernel<<<dim3(32, 32), dim3(32, 32)>>>(Wo, pWth + 3 * WSZ, pWtl + 3 * WSZ);

    dim3 gemmGrid(D_ / 128, BN_ / 128);  // (8, 128)

    // 1. QKV projections (mma.sync bf16-split)
    gemm_bf16x3<<<gemmGrid, 256, GSMEM>>>(pxh, pxl, pWth + 0 * WSZ, pWtl + 0 * WSZ, pQ);
    gemm_bf16x3<<<gemmGrid, 256, GSMEM>>>(pxh, pxl, pWth + 1 * WSZ, pWtl + 1 * WSZ, pK);
    gemm_bf16x3<<<gemmGrid, 256, GSMEM>>>(pxh, pxl, pWth + 2 * WSZ, pWtl + 2 * WSZ, pV);

    // 2. FAVOR+ features
    feat_kernel<0><<<ROWS_, 128>>>(pQ, proj, pqf, nullptr, nullptr);
    feat_kernel<1><<<ROWS_, 128>>>(pK, proj, pkf, pkd, prm);
    kmax_reduce_kernel<<<B_ * H_, 256>>>(prm, pkm);
    kfeat2_kernel<<<ROWS_, 128>>>(pkf, pkd, pkm);

    // 3. Linear attention
    ksum_kernel<<<B_ * H_, 288>>>(pkf, pks);
    ctx_kernel<<<dim3(9, B_ * H_), 256>>>(pkf, pV, pctx);
    dinv_kernel<<<ROWS_ / 8, 256>>>(pqf, pks, pdi);
    attn_out_kernel<<<dim3(N_ / 16, B_ * H_), 256>>>(pqf, pctx, pdi, pah, pal);

    // 4. Output projection + residual + LayerNorm
    gemm_bf16x3<<<gemmGrid, 256, GSMEM>>>(pah, pal, pWth + 3 * WSZ, pWtl + 3 * WSZ, po2);
    ln_kernel<<<BN_, 256>>>(x, po2, bo, gamma, beta, out);
}

// round 4
// speedup vs baseline: 9.3272x; 8.7725x over previous
#include <cuda_runtime.h>
#include <cuda_bf16.h>
#include <cstdint>
#include <cstddef>

// Problem constants
#define B_  4
#define N_  4096
#define H_  16
#define DH_ 64
#define M_  266
#define D_  1024
#define ROWS_ (B_*H_*N_)        // 262144
#define BN_   (B_*N_)           // 16384

#define DN_    0.3535533906f    // 64^-0.25
#define RATIO_ 0.0613139315f    // 266^-0.5
#define EPS_F  1e-4f
#define EPS_LN 1e-5f

// ------------------------- scratch (device globals) -------------------------
__device__ float g_Q[(size_t)BN_ * D_];
__device__ float g_K[(size_t)BN_ * D_];
__device__ float g_V[(size_t)BN_ * D_];
__device__ float g_qf[(size_t)ROWS_ * M_];
__device__ float g_kf[(size_t)ROWS_ * M_];
__device__ float g_kdiag[ROWS_];
__device__ float g_krowmax[ROWS_];
__device__ float g_qdiag[ROWS_];
__device__ float g_qrowmax[ROWS_];
__device__ float g_kmax[B_ * H_];
__device__ float g_ksum[B_ * H_ * M_];
__device__ float g_ksum_part[B_ * H_ * 16 * 272];
__device__ float g_ctx[(size_t)B_ * H_ * M_ * DH_];
__device__ float g_dinv[ROWS_];
__device__ float g_out2[(size_t)BN_ * D_];

// split operands (bf16 hi/lo)
__device__ __nv_bfloat16 g_xh[(size_t)BN_ * D_];
__device__ __nv_bfloat16 g_xl[(size_t)BN_ * D_];
__device__ __nv_bfloat16 g_ah[(size_t)BN_ * D_];
__device__ __nv_bfloat16 g_al[(size_t)BN_ * D_];
__device__ __nv_bfloat16 g_Wth[4][(size_t)D_ * D_];  // W^T hi: [n][k]
__device__ __nv_bfloat16 g_Wtl[4][(size_t)D_ * D_];  // W^T lo

// ------------------------- helpers ------------------------------------------
__device__ __forceinline__ uint32_t smem_u32(const void* p) {
    uint32_t a;
    asm("{ .reg .u64 t; cvta.to.shared.u64 t, %1; cvt.u32.u64 %0, t; }" : "=r"(a) : "l"(p));
    return a;
}

__device__ __forceinline__ void ldm_x4(uint32_t addr, uint32_t& r0, uint32_t& r1,
                                       uint32_t& r2, uint32_t& r3) {
    asm volatile("ldmatrix.sync.aligned.m8n8.x4.shared.b16 {%0,%1,%2,%3}, [%4];"
                 : "=r"(r0), "=r"(r1), "=r"(r2), "=r"(r3) : "r"(addr));
}

__device__ __forceinline__ void mma_bf16(float* c, const uint32_t* a, const uint32_t* b) {
    asm volatile(
        "mma.sync.aligned.m16n8k16.row.col.f32.bf16.bf16.f32 "
        "{%0,%1,%2,%3}, {%4,%5,%6,%7}, {%8,%9}, {%0,%1,%2,%3};"
        : "+f"(c[0]), "+f"(c[1]), "+f"(c[2]), "+f"(c[3])
        : "r"(a[0]), "r"(a[1]), "r"(a[2]), "r"(a[3]), "r"(b[0]), "r"(b[1]));
}

// ------------------------- split / transpose kernels ------------------------
__global__ __launch_bounds__(256) void split_x_kernel(const float* __restrict__ x,
                                                      __nv_bfloat16* __restrict__ xh,
                                                      __nv_bfloat16* __restrict__ xl) {
    const size_t i = ((size_t)blockIdx.x * 256 + threadIdx.x) * 4;
    float4 v = *(const float4*)(x + i);
    float a[4] = {v.x, v.y, v.z, v.w};
#pragma unroll
    for (int j = 0; j < 4; j++) {
        __nv_bfloat16 h = __float2bfloat16(a[j]);
        xh[i + j] = h;
        xl[i + j] = __float2bfloat16(a[j] - __bfloat162float(h));
    }
}

// transpose + split: Th[n][k] = bf16(W[k][n]); Tl = residual
__global__ __launch_bounds__(1024) void splitT_W_kernel(const float* __restrict__ W,
                                                        __nv_bfloat16* __restrict__ Th,
                                                        __nv_bfloat16* __restrict__ Tl) {
    __shared__ float tile[32][33];
    const int n = blockIdx.x * 32 + threadIdx.x;
    const int k = blockIdx.y * 32 + threadIdx.y;
    tile[threadIdx.y][threadIdx.x] = W[(size_t)k * D_ + n];
    __syncthreads();
    const float v = tile[threadIdx.x][threadIdx.y];
    const int on = blockIdx.x * 32 + threadIdx.y;
    const int ok = blockIdx.y * 32 + threadIdx.x;
    __nv_bfloat16 h = __float2bfloat16(v);
    Th[(size_t)on * D_ + ok] = h;
    Tl[(size_t)on * D_ + ok] = __float2bfloat16(v - __bfloat162float(h));
}

// ------------------------- mma.sync bf16-split GEMM -------------------------
// C[16384 x 1024] = (Ah+Al) * (Bh+Bl)^T; B stored [N=1024][K=1024].
// CTA tile 128x128, warp tile 64x32 (2x4 warps), KC=32 double-buffered.
#define KC    32
#define PITCH 80                    // bytes per smem row (64 data + 16 pad)
#define OPB   (128 * PITCH)         // 10240 bytes per operand tile
#define STAGEB (4 * OPB)            // Ah, Al, Bh, Bl
#define GSMEM (2 * STAGEB)          // 81920

__global__ __launch_bounds__(256, 1) void gemm_bf16x3(
    const __nv_bfloat16* __restrict__ Ah, const __nv_bfloat16* __restrict__ Al,
    const __nv_bfloat16* __restrict__ Bh, const __nv_bfloat16* __restrict__ Bl,
    float* __restrict__ C) {
    extern __shared__ char smem[];
    const uint32_t sb = smem_u32(smem);
    const int tid = threadIdx.x;
    const int wid = tid >> 5;
    const int lid = tid & 31;
    const int warp_m = wid & 1;       // 0..1
    const int warp_n = wid >> 1;      // 0..3
    const int row0 = blockIdx.y * 128;
    const int col0 = blockIdx.x * 128;

    const __nv_bfloat16* gA[2] = {Ah + (size_t)row0 * D_, Al + (size_t)row0 * D_};
    const __nv_bfloat16* gB[2] = {Bh + (size_t)col0 * D_, Bl + (size_t)col0 * D_};

    const int r0i = (tid * 2) >> 2;
    const int s0i = (tid * 2) & 3;
    const int r1i = (tid * 2 + 1) >> 2;
    const int s1i = (tid * 2 + 1) & 3;

    const uint32_t a_base = (uint32_t)((warp_m * 64 + (lid & 15)) * PITCH + (lid >> 4) * 16);
    const uint32_t b_base = (uint32_t)((warp_n * 32 + ((lid >> 4) * 8) + (lid & 7)) * PITCH +
                                       ((lid >> 3) & 1) * 16);

    float acc[4][4][4];
#pragma unroll
    for (int mi = 0; mi < 4; mi++)
#pragma unroll
        for (int ni = 0; ni < 4; ni++)
#pragma unroll
            for (int q = 0; q < 4; q++) acc[mi][ni][q] = 0.f;

    uint4 pf[4][2];
#pragma unroll
    for (int o = 0; o < 2; o++) {
        pf[o][0]     = *(const uint4*)(gA[o] + (size_t)r0i * D_ + s0i * 8);
        pf[o][1]     = *(const uint4*)(gA[o] + (size_t)r1i * D_ + s1i * 8);
        pf[o + 2][0] = *(const uint4*)(gB[o] + (size_t)r0i * D_ + s0i * 8);
        pf[o + 2][1] = *(const uint4*)(gB[o] + (size_t)r1i * D_ + s1i * 8);
    }

    for (int c = 0; c < D_ / KC; c++) {
        const uint32_t stage = (c & 1) * STAGEB;
#pragma unroll
        for (int o = 0; o < 4; o++) {
            *(uint4*)(smem + stage + o * OPB + r0i * PITCH + s0i * 16) = pf[o][0];
            *(uint4*)(smem + stage + o * OPB + r1i * PITCH + s1i * 16) = pf[o][1];
        }
        __syncthreads();

        if (c + 1 < D_ / KC) {
            const int k0 = (c + 1) * KC;
#pragma unroll
            for (int o = 0; o < 2; o++) {
                pf[o][0]     = *(const uint4*)(gA[o] + (size_t)r0i * D_ + k0 + s0i * 8);
                pf[o][1]     = *(const uint4*)(gA[o] + (size_t)r1i * D_ + k0 + s1i * 8);
                pf[o + 2][0] = *(const uint4*)(gB[o] + (size_t)r0i * D_ + k0 + s0i * 8);
                pf[o + 2][1] = *(const uint4*)(gB[o] + (size_t)r1i * D_ + k0 + s1i * 8);
            }
        }

        const uint32_t sAh = sb + stage;
        const uint32_t sAl = sb + stage + OPB;
        const uint32_t sBh = sb + stage + 2 * OPB;
        const uint32_t sBl = sb + stage + 3 * OPB;

#pragma unroll
        for (int ks = 0; ks < 2; ks++) {
            const uint32_t kb = ks * 32;
            uint32_t ah[4][4], al[4][4], bh[4][2], bl[4][2];
#pragma unroll
            for (int mi = 0; mi < 4; mi++) {
                const uint32_t ao = a_base + mi * 16 * PITCH + kb;
                ldm_x4(sAh + ao, ah[mi][0], ah[mi][1], ah[mi][2], ah[mi][3]);
                ldm_x4(sAl + ao, al[mi][0], al[mi][1], al[mi][2], al[mi][3]);
            }
#pragma unroll
            for (int p = 0; p < 2; p++) {
                const uint32_t bo = b_base + p * 16 * PITCH + kb;
                ldm_x4(sBh + bo, bh[2 * p][0], bh[2 * p][1], bh[2 * p + 1][0], bh[2 * p + 1][1]);
                ldm_x4(sBl + bo, bl[2 * p][0], bl[2 * p][1], bl[2 * p + 1][0], bl[2 * p + 1][1]);
            }
#pragma unroll
            for (int mi = 0; mi < 4; mi++)
#pragma unroll
                for (int ni = 0; ni < 4; ni++) {
                    mma_bf16(acc[mi][ni], ah[mi], bh[ni]);
                    mma_bf16(acc[mi][ni], ah[mi], bl[ni]);
                    mma_bf16(acc[mi][ni], al[mi], bh[ni]);
                }
        }
        __syncthreads();
    }

    const int g = lid >> 2, tg = lid & 3;
#pragma unroll
    for (int mi = 0; mi < 4; mi++) {
#pragma unroll
        for (int ni = 0; ni < 4; ni++) {
            const int row = row0 + warp_m * 64 + mi * 16 + g;
            const int col = col0 + warp_n * 32 + ni * 8 + tg * 2;
            float2 v0 = {acc[mi][ni][0], acc[mi][ni][1]};
            float2 v1 = {acc[mi][ni][2], acc[mi][ni][3]};
            *(float2*)(C + (size_t)row * D_ + col) = v0;
            *(float2*)(C + (size_t)(row + 8) * D_ + col) = v1;
        }
    }
}

// ------------------------- FAVOR+ feature map (tiled) -----------------------
// One block: 64 rows of one (b,h). xd = (x*DN) @ proj^T written raw to fout;
// per-row max -> rowmax_out, 0.5*||xs||^2 -> diag_out.
// smem: xst[64][65] (xst[k][r]) + prs[128][65] (prs[mm][k]) = 49920 B.
#define FEAT_SMEM ((64 * 65 + 128 * 65) * 4)

__global__ __launch_bounds__(256) void feat_raw_kernel(const float* __restrict__ QK,
                                                       const float* __restrict__ proj,
                                                       float* __restrict__ fout,
                                                       float* __restrict__ diag_out,
                                                       float* __restrict__ rowmax_out) {
    const int bh = blockIdx.y;
    const int n0 = blockIdx.x * 64;
    const int b = bh >> 4, h = bh & 15;
    const int t = threadIdx.x;
    const int lane = t & 31;
    const int tr = t >> 5;          // warp id = row group
    extern __shared__ float fsm[];
    float* xst = fsm;               // [64][65]
    float* prs = fsm + 64 * 65;     // [128][65]
    const size_t idx0 = (size_t)bh * N_ + n0;

    // load x tile transposed, scaled by DN_
#pragma unroll
    for (int p4 = 0; p4 < 4; p4++) {
        const int f4 = t + p4 * 256;
        const int r = f4 >> 4;
        const int kq = (f4 & 15) * 4;
        float4 v = *(const float4*)(QK + ((size_t)(b * N_ + n0 + r)) * D_ + h * 64 + kq);
        xst[(kq + 0) * 65 + r] = v.x * DN_;
        xst[(kq + 1) * 65 + r] = v.y * DN_;
        xst[(kq + 2) * 65 + r] = v.z * DN_;
        xst[(kq + 3) * 65 + r] = v.w * DN_;
    }
    __syncthreads();

    // diag per row
    if (t < 64) {
        float s = 0.f;
#pragma unroll 16
        for (int k = 0; k < 64; k++) {
            const float v = xst[k * 65 + t];
            s += v * v;
        }
        diag_out[idx0 + t] = 0.5f * s;
    }

    float lmax[8];
#pragma unroll
    for (int j = 0; j < 8; j++) lmax[j] = -1e30f;

    for (int p = 0; p < 3; p++) {
        __syncthreads();
        // stage proj rows p*128 .. p*128+127 (clamped) as prs[mm][k]
#pragma unroll
        for (int p4 = 0; p4 < 8; p4++) {
            const int f4 = t + p4 * 256;
            const int mm = f4 >> 4;
            const int kq = (f4 & 15) * 4;
            int gm = p * 128 + mm;
            if (gm > M_ - 1) gm = M_ - 1;
            float4 v = *(const float4*)(proj + (size_t)gm * 64 + kq);
            prs[mm * 65 + kq + 0] = v.x;
            prs[mm * 65 + kq + 1] = v.y;
            prs[mm * 65 + kq + 2] = v.z;
            prs[mm * 65 + kq + 3] = v.w;
        }
        __syncthreads();

        float acc[8][4];
#pragma unroll
        for (int j = 0; j < 8; j++)
#pragma unroll
            for (int jm = 0; jm < 4; jm++) acc[j][jm] = 0.f;

#pragma unroll 8
        for (int k = 0; k < 64; k++) {
            float xv[8], pv[4];
#pragma unroll
            for (int j = 0; j < 8; j++) xv[j] = xst[k * 65 + tr * 8 + j];      // broadcast
#pragma unroll
            for (int jm = 0; jm < 4; jm++) pv[jm] = prs[(lane + 32 * jm) * 65 + k];  // conflict-free
#pragma unroll
            for (int j = 0; j < 8; j++)
#pragma unroll
                for (int jm = 0; jm < 4; jm++) acc[j][jm] += xv[j] * pv[jm];
        }

#pragma unroll
        for (int jm = 0; jm < 4; jm++) {
            const int m = p * 128 + lane + 32 * jm;
            if (m < M_) {
#pragma unroll
                for (int j = 0; j < 8; j++) {
                    fout[(idx0 + tr * 8 + j) * M_ + m] = acc[j][jm];
                    lmax[j] = fmaxf(lmax[j], acc[j][jm]);
                }
            }
        }
    }

    // warp-reduce row maxima (all lanes of a warp own the same 8 rows)
#pragma unroll
    for (int off = 16; off > 0; off >>= 1)
#pragma unroll
        for (int j = 0; j < 8; j++)
            lmax[j] = fmaxf(lmax[j], __shfl_xor_sync(0xffffffffu, lmax[j], off));
    if (lane == 0) {
#pragma unroll
        for (int j = 0; j < 8; j++) rowmax_out[idx0 + tr * 8 + j] = lmax[j];
    }
}

// exp pass, per-row stabilizer (queries)
__global__ __launch_bounds__(128) void qfeat2_kernel(float* __restrict__ qf,
                                                     const float* __restrict__ qdiag,
                                                     const float* __restrict__ qrowmax) {
    const int idx = blockIdx.x;
    const float sub = qdiag[idx] + qrowmax[idx];
    float* row = qf + (size_t)idx * M_;
    for (int m = threadIdx.x; m < M_; m += 128)
        row[m] = RATIO_ * (expf(row[m] - sub) + EPS_F);
}

__global__ __launch_bounds__(256) void kmax_reduce_kernel(const float* __restrict__ rowmax,
                                                          float* __restrict__ kmax) {
    __shared__ float sm[256];
    const int bh = blockIdx.x;
    float v = -1e30f;
    for (int i = threadIdx.x; i < N_; i += 256)
        v = fmaxf(v, rowmax[bh * N_ + i]);
    sm[threadIdx.x] = v;
    __syncthreads();
#pragma unroll
    for (int off = 128; off > 0; off >>= 1) {
        if (threadIdx.x < off) sm[threadIdx.x] = fmaxf(sm[threadIdx.x], sm[threadIdx.x + off]);
        __syncthreads();
    }
    if (threadIdx.x == 0) kmax[bh] = sm[0];
}

// exp pass, per-(b,h) stabilizer (keys)
__global__ __launch_bounds__(128) void kfeat2_kernel(float* __restrict__ kf,
                                                     const float* __restrict__ kdiag,
                                                     const float* __restrict__ kmax) {
    const int idx = blockIdx.x;
    const int bh = idx >> 12;
    const float sub = kdiag[idx] + kmax[bh];
    float* row = kf + (size_t)idx * M_;
    for (int m = threadIdx.x; m < M_; m += 128)
        row[m] = RATIO_ * (expf(row[m] - sub) + EPS_F);
}

// ------------------------- linear attention ---------------------------------
// two-stage ksum
__global__ __launch_bounds__(288) void ksum_part_kernel(const float* __restrict__ kf,
                                                        float* __restrict__ part) {
    const int bh = blockIdx.y;
    const int c = blockIdx.x;    // 16 chunks of 256 rows
    const int m = threadIdx.x;
    if (m >= M_) return;
    float s = 0.f;
    const float* base = kf + ((size_t)bh * N_ + c * 256) * M_ + m;
    for (int n = 0; n < 256; n++) s += base[(size_t)n * M_];
    part[((size_t)bh * 16 + c) * 272 + m] = s;
}

__global__ __launch_bounds__(288) void ksum_final_kernel(const float* __restrict__ part,
                                                         float* __restrict__ ksum) {
    const int bh = blockIdx.x;
    const int m = threadIdx.x;
    if (m >= M_) return;
    float s = 0.f;
#pragma unroll
    for (int c = 0; c < 16; c++) s += part[((size_t)bh * 16 + c) * 272 + m];
    ksum[bh * M_ + m] = s;
}

__global__ __launch_bounds__(256) void ctx_kernel(const float* __restrict__ kf,
                                                  const float* __restrict__ V,
                                                  float* __restrict__ ctx) {
    __shared__ float Ks[32][32];
    __shared__ float Vs[32][64];

    const int bh = blockIdx.y;
    const int b = bh >> 4, h = bh & 15;
    const int m0 = blockIdx.x * 32;
    const int t = threadIdx.x;
    const int d = t & 63;
    const int mb = (t >> 6) * 8;

    float acc[8];
#pragma unroll
    for (int j = 0; j < 8; j++) acc[j] = 0.f;

    for (int n0 = 0; n0 < N_; n0 += 32) {
#pragma unroll
        for (int q = 0; q < 4; q++) {
            const int idx = t + q * 256;
            const int i = idx >> 5, j = idx & 31;
            const int m = m0 + j;
            Ks[i][j] = (m < M_) ? kf[((size_t)(bh * N_ + n0 + i)) * M_ + m] : 0.f;
        }
#pragma unroll
        for (int q = 0; q < 8; q++) {
            const int idx = t + q * 256;
            const int i = idx >> 6, dd = idx & 63;
            Vs[i][dd] = V[((size_t)(b * N_ + n0 + i)) * D_ + h * 64 + dd];
        }
        __syncthreads();
#pragma unroll 8
        for (int i = 0; i < 32; i++) {
            const float vv = Vs[i][d];
#pragma unroll
            for (int j = 0; j < 8; j++) acc[j] += Ks[i][mb + j] * vv;
        }
        __syncthreads();
    }

#pragma unroll
    for (int j = 0; j < 8; j++) {
        const int m = m0 + mb + j;
        if (m < M_) ctx[((size_t)bh * M_ + m) * 64 + d] = acc[j];
    }
}

__global__ __launch_bounds__(256) void dinv_kernel(const float* __restrict__ qf,
                                                   const float* __restrict__ ksum,
                                                   float* __restrict__ dinv) {
    const int row = blockIdx.x * 8 + (threadIdx.x >> 5);
    const int lane = threadIdx.x & 31;
    const int bh = row >> 12;
    float s = 0.f;
    const float* qr = qf + (size_t)row * M_;
    const float* ks = ksum + bh * M_;
    for (int m = lane; m < M_; m += 32) s += qr[m] * ks[m];
#pragma unroll
    for (int off = 16; off > 0; off >>= 1) s += __shfl_xor_sync(0xffffffff, s, off);
    if (lane == 0) dinv[row] = 1.f / s;
}

// out -> split bf16 (for Wo mma GEMM)
__global__ __launch_bounds__(256) void attn_out_kernel(const float* __restrict__ qf,
                                                       const float* __restrict__ ctx,
                                                       const float* __restrict__ dinv,
                                                       __nv_bfloat16* __restrict__ ah,
                                                       __nv_bfloat16* __restrict__ al) {
    __shared__ float Cs[64][64];
    __shared__ float Qs[16][64];

    const int bh = blockIdx.y;
    const int b = bh >> 4, h = bh & 15;
    const int n0 = blockIdx.x * 16;
    const int t = threadIdx.x;
    const int d = t & 63;
    const int rg = (t >> 6) * 4;

    float acc[4] = {0.f, 0.f, 0.f, 0.f};

    for (int c = 0; c < 5; c++) {
        const int m0 = c * 64;
        const int mw = (M_ - m0 < 64) ? (M_ - m0) : 64;
#pragma unroll
        for (int q = 0; q < 16; q++) {
            const int idx = t + q * 256;
            const int mm = idx >> 6, dd = idx & 63;
            Cs[mm][dd] = (mm < mw) ? ctx[((size_t)bh * M_ + m0 + mm) * 64 + dd] : 0.f;
        }
#pragma unroll
        for (int q = 0; q < 4; q++) {
            const int idx = t + q * 256;
            const int r = idx >> 6, mm = idx & 63;
            Qs[r][mm] = (mm < mw) ? qf[((size_t)(bh * N_ + n0 + r)) * M_ + m0 + mm] : 0.f;
        }
        __syncthreads();
#pragma unroll 8
        for (int mm = 0; mm < 64; mm++) {
            const float cv = Cs[mm][d];
#pragma unroll
            for (int ii = 0; ii < 4; ii++) acc[ii] += Qs[rg + ii][mm] * cv;
        }
        __syncthreads();
    }

#pragma unroll
    for (int ii = 0; ii < 4; ii++) {
        const int n = n0 + rg + ii;
        const float v = acc[ii] * dinv[bh * N_ + n];
        const size_t o = ((size_t)(b * N_ + n)) * D_ + h * 64 + d;
        __nv_bfloat16 hv = __float2bfloat16(v);
        ah[o] = hv;
        al[o] = __float2bfloat16(v - __bfloat162float(hv));
    }
}

// ------------------------- residual + LayerNorm -----------------------------
__global__ __launch_bounds__(256) void ln_kernel(const float* __restrict__ x,
                                                 const float* __restrict__ o2,
                                                 const float* __restrict__ bo,
                                                 const float* __restrict__ gamma,
                                                 const float* __restrict__ beta,
                                                 float* __restrict__ out) {
    __shared__ float ss[256];
    __shared__ float sq[256];
    const int row = blockIdx.x;
    const int t = threadIdx.x;
    const size_t base = (size_t)row * D_;

    float yv[4];
    float s = 0.f, q = 0.f;
#pragma unroll
    for (int i = 0; i < 4; i++) {
        const int c = t + i * 256;
        const float v = x[base + c] + o2[base + c] + bo[c];
        yv[i] = v;
        s += v;
        q += v * v;
    }
    ss[t] = s;
    sq[t] = q;
    __syncthreads();
#pragma unroll
    for (int off = 128; off > 0; off >>= 1) {
        if (t < off) { ss[t] += ss[t + off]; sq[t] += sq[t + off]; }
        __syncthreads();
    }
    const float mu = ss[0] * (1.f / (float)D_);
    const float var = sq[0] * (1.f / (float)D_) - mu * mu;
    const float rstd = rsqrtf(var + EPS_LN);
#pragma unroll
    for (int i = 0; i < 4; i++) {
        const int c = t + i * 256;
        out[base + c] = (yv[i] - mu) * rstd * gamma[c] + beta[c];
    }
}

// ------------------------- launch --------------------------------------------
extern "C" void kernel_launch(void* const* d_in, const int* in_sizes, int n_in,
                              void* d_out, int out_size) {
    const float* x     = (const float*)d_in[0];
    const float* Wq    = (const float*)d_in[1];
    const float* Wk    = (const float*)d_in[2];
    const float* Wv    = (const float*)d_in[3];
    const float* Wo    = (const float*)d_in[4];
    const float* bo    = (const float*)d_in[5];
    const float* proj  = (const float*)d_in[6];
    const float* gamma = (const float*)d_in[7];
    const float* beta  = (const float*)d_in[8];
    float* out = (float*)d_out;

    float *pQ, *pK, *pV, *pqf, *pkf, *pkd, *prm, *pqd, *pqrm, *pkm, *pks, *pksp, *pctx, *pdi, *po2;
    __nv_bfloat16 *pxh, *pxl, *pah, *pal, *pWth, *pWtl;
    cudaGetSymbolAddress((void**)&pQ,   g_Q);
    cudaGetSymbolAddress((void**)&pK,   g_K);
    cudaGetSymbolAddress((void**)&pV,   g_V);
    cudaGetSymbolAddress((void**)&pqf,  g_qf);
    cudaGetSymbolAddress((void**)&pkf,  g_kf);
    cudaGetSymbolAddress((void**)&pkd,  g_kdiag);
    cudaGetSymbolAddress((void**)&prm,  g_krowmax);
    cudaGetSymbolAddress((void**)&pqd,  g_qdiag);
    cudaGetSymbolAddress((void**)&pqrm, g_qrowmax);
    cudaGetSymbolAddress((void**)&pkm,  g_kmax);
    cudaGetSymbolAddress((void**)&pks,  g_ksum);
    cudaGetSymbolAddress((void**)&pksp, g_ksum_part);
    cudaGetSymbolAddress((void**)&pctx, g_ctx);
    cudaGetSymbolAddress((void**)&pdi,  g_dinv);
    cudaGetSymbolAddress((void**)&po2,  g_out2);
    cudaGetSymbolAddress((void**)&pxh,  g_xh);
    cudaGetSymbolAddress((void**)&pxl,  g_xl);
    cudaGetSymbolAddress((void**)&pah,  g_ah);
    cudaGetSymbolAddress((void**)&pal,  g_al);
    cudaGetSymbolAddress((void**)&pWth, g_Wth);
    cudaGetSymbolAddress((void**)&pWtl, g_Wtl);

    cudaFuncSetAttribute(gemm_bf16x3, cudaFuncAttributeMaxDynamicSharedMemorySize, GSMEM);
    cudaFuncSetAttribute(feat_raw_kernel, cudaFuncAttributeMaxDynamicSharedMemorySize, FEAT_SMEM);

    const size_t WSZ = (size_t)D_ * D_;

    // 0. operand prep
    split_x_kernel<<<BN_ * D_ / (256 * 4), 256>>>(x, pxh, pxl);
    splitT_W_kernel<<<dim3(32, 32), dim3(32, 32)>>>(Wq, pWth + 0 * WSZ, pWtl + 0 * WSZ);
    splitT_W_kernel<<<dim3(32, 32), dim3(32, 32)>>>(Wk, pWth + 1 * WSZ, pWtl + 1 * WSZ);
    splitT_W_kernel<<<dim3(32, 32), dim3(32, 32)>>>(Wv, pWth + 2 * WSZ, pWtl + 2 * WSZ);
    splitT_W_kernel<<<dim3(32, 32), dim3(32, 32)>>>(Wo, pWth + 3 * WSZ, pWtl + 3 * WSZ);

    dim3 gemmGrid(D_ / 128, BN_ / 128);  // (8, 128)

    // 1. QKV projections (mma.sync bf16-split)
    gemm_bf16x3<<<gemmGrid, 256, GSMEM>>>(pxh, pxl, pWth + 0 * WSZ, pWtl + 0 * WSZ, pQ);
    gemm_bf16x3<<<gemmGrid, 256, GSMEM>>>(pxh, pxl, pWth + 1 * WSZ, pWtl + 1 * WSZ, pK);
    gemm_bf16x3<<<gemmGrid, 256, GSMEM>>>(pxh, pxl, pWth + 2 * WSZ, pWtl + 2 * WSZ, pV);

    // 2. FAVOR+ features (tiled raw xd + exp passes)
    dim3 featGrid(N_ / 64, B_ * H_);     // (64, 64)
    feat_raw_kernel<<<featGrid, 256, FEAT_SMEM>>>(pQ, proj, pqf, pqd, pqrm);
    feat_raw_kernel<<<featGrid, 256, FEAT_SMEM>>>(pK, proj, pkf, pkd, prm);
    qfeat2_kernel<<<ROWS_, 128>>>(pqf, pqd, pqrm);
    kmax_reduce_kernel<<<B_ * H_, 256>>>(prm, pkm);
    kfeat2_kernel<<<ROWS_, 128>>>(pkf, pkd, pkm);

    // 3. Linear attention
    ksum_part_kernel<<<dim3(16, B_ * H_), 288>>>(pkf, pksp);
    ksum_final_kernel<<<B_ * H_, 288>>>(pksp, pks);
    ctx_kernel<<<dim3(9, B_ * H_), 256>>>(pkf, pV, pctx);
    dinv_kernel<<<ROWS_ / 8, 256>>>(pqf, pks, pdi);
    attn_out_kernel<<<dim3(N_ / 16, B_ * H_), 256>>>(pqf, pctx, pdi, pah, pal);

    // 4. Output projection + residual + LayerNorm
    gemm_bf16x3<<<gemmGrid, 256, GSMEM>>>(pah, pal, pWth + 3 * WSZ, pWtl + 3 * WSZ, po2);
    ln_kernel<<<BN_, 256>>>(x, po2, bo, gamma, beta, out);
}

// round 5
// speedup vs baseline: 10.7778x; 1.1555x over previous
#include <cuda_runtime.h>
#include <cuda_bf16.h>
#include <cstdint>
#include <cstddef>

// Problem constants
#define B_  4
#define N_  4096
#define H_  16
#define DH_ 64
#define M_  266
#define D_  1024
#define ROWS_ (B_*H_*N_)        // 262144
#define BN_   (B_*N_)           // 16384

#define DN_    0.3535533906f    // 64^-0.25
#define RATIO_ 0.0613139315f    // 266^-0.5
#define EPS_F  1e-4f
#define EPS_LN 1e-5f

// ------------------------- scratch (device globals) -------------------------
__device__ float g_Q[(size_t)BN_ * D_];
__device__ float g_K[(size_t)BN_ * D_];
__device__ float g_V[(size_t)BN_ * D_];
__device__ float g_qf[(size_t)ROWS_ * M_];
__device__ float g_kf[(size_t)ROWS_ * M_];       // raw xd for keys
__device__ float g_kdiag[ROWS_];
__device__ float g_krowmax[ROWS_];
__device__ float g_kmax[B_ * H_];
__device__ float g_ksum[B_ * H_ * M_];
__device__ float g_ksum_part[B_ * H_ * 16 * 272];
__device__ float g_ctx[(size_t)B_ * H_ * M_ * DH_];
__device__ float g_out2[(size_t)BN_ * D_];

// split operands (bf16 hi/lo)
__device__ __nv_bfloat16 g_xh[(size_t)BN_ * D_];
__device__ __nv_bfloat16 g_xl[(size_t)BN_ * D_];
__device__ __nv_bfloat16 g_ah[(size_t)BN_ * D_];
__device__ __nv_bfloat16 g_al[(size_t)BN_ * D_];
__device__ __nv_bfloat16 g_Wth[4][(size_t)D_ * D_];  // W^T hi: [n][k]
__device__ __nv_bfloat16 g_Wtl[4][(size_t)D_ * D_];  // W^T lo

// ------------------------- helpers ------------------------------------------
__device__ __forceinline__ uint32_t smem_u32(const void* p) {
    uint32_t a;
    asm("{ .reg .u64 t; cvta.to.shared.u64 t, %1; cvt.u32.u64 %0, t; }" : "=r"(a) : "l"(p));
    return a;
}

__device__ __forceinline__ void ldm_x4(uint32_t addr, uint32_t& r0, uint32_t& r1,
                                       uint32_t& r2, uint32_t& r3) {
    asm volatile("ldmatrix.sync.aligned.m8n8.x4.shared.b16 {%0,%1,%2,%3}, [%4];"
                 : "=r"(r0), "=r"(r1), "=r"(r2), "=r"(r3) : "r"(addr));
}

__device__ __forceinline__ void mma_bf16(float* c, const uint32_t* a, const uint32_t* b) {
    asm volatile(
        "mma.sync.aligned.m16n8k16.row.col.f32.bf16.bf16.f32 "
        "{%0,%1,%2,%3}, {%4,%5,%6,%7}, {%8,%9}, {%0,%1,%2,%3};"
        : "+f"(c[0]), "+f"(c[1]), "+f"(c[2]), "+f"(c[3])
        : "r"(a[0]), "r"(a[1]), "r"(a[2]), "r"(a[3]), "r"(b[0]), "r"(b[1]));
}

__device__ __forceinline__ void cp16(uint32_t saddr, const void* gptr) {
    asm volatile("cp.async.cg.shared.global [%0], [%1], 16;" :: "r"(saddr), "l"(gptr));
}
#define CP_COMMIT() asm volatile("cp.async.commit_group;" ::: "memory")
#define CP_WAIT(n)  asm volatile("cp.async.wait_group %0;" :: "n"(n) : "memory")

// ------------------------- split / transpose kernels ------------------------
__global__ __launch_bounds__(256) void split_x_kernel(const float* __restrict__ x,
                                                      __nv_bfloat16* __restrict__ xh,
                                                      __nv_bfloat16* __restrict__ xl) {
    const size_t i = ((size_t)blockIdx.x * 256 + threadIdx.x) * 4;
    float4 v = *(const float4*)(x + i);
    float a[4] = {v.x, v.y, v.z, v.w};
#pragma unroll
    for (int j = 0; j < 4; j++) {
        __nv_bfloat16 h = __float2bfloat16(a[j]);
        xh[i + j] = h;
        xl[i + j] = __float2bfloat16(a[j] - __bfloat162float(h));
    }
}

__global__ __launch_bounds__(1024) void splitT_W_kernel(const float* __restrict__ W,
                                                        __nv_bfloat16* __restrict__ Th,
                                                        __nv_bfloat16* __restrict__ Tl) {
    __shared__ float tile[32][33];
    const int n = blockIdx.x * 32 + threadIdx.x;
    const int k = blockIdx.y * 32 + threadIdx.y;
    tile[threadIdx.y][threadIdx.x] = W[(size_t)k * D_ + n];
    __syncthreads();
    const float v = tile[threadIdx.x][threadIdx.y];
    const int on = blockIdx.x * 32 + threadIdx.y;
    const int ok = blockIdx.y * 32 + threadIdx.x;
    __nv_bfloat16 h = __float2bfloat16(v);
    Th[(size_t)on * D_ + ok] = h;
    Tl[(size_t)on * D_ + ok] = __float2bfloat16(v - __bfloat162float(h));
}

// ------------------------- mma.sync bf16-split GEMM, cp.async 3-stage -------
#define KC    32
#define PITCH 80                    // bytes per smem row (64 data + 16 pad)
#define OPB   (128 * PITCH)         // 10240 bytes per operand tile
#define STAGEB (4 * OPB)            // Ah, Al, Bh, Bl = 40960
#define NST   3
#define GSMEM (NST * STAGEB)        // 122880

__global__ __launch_bounds__(256, 1) void gemm_bf16x3(
    const __nv_bfloat16* __restrict__ Ah, const __nv_bfloat16* __restrict__ Al,
    const __nv_bfloat16* __restrict__ Bh, const __nv_bfloat16* __restrict__ Bl,
    float* __restrict__ C) {
    extern __shared__ char smem[];
    const uint32_t sb = smem_u32(smem);
    const int tid = threadIdx.x;
    const int wid = tid >> 5;
    const int lid = tid & 31;
    const int warp_m = wid & 1;
    const int warp_n = wid >> 1;
    const int row0 = blockIdx.y * 128;
    const int col0 = blockIdx.x * 128;

    const __nv_bfloat16* gOp[4] = {Ah + (size_t)row0 * D_, Al + (size_t)row0 * D_,
                                   Bh + (size_t)col0 * D_, Bl + (size_t)col0 * D_};

    const int r0i = (tid * 2) >> 2;
    const int s0i = (tid * 2) & 3;
    const int r1i = (tid * 2 + 1) >> 2;
    const int s1i = (tid * 2 + 1) & 3;

    const uint32_t a_base = (uint32_t)((warp_m * 64 + (lid & 15)) * PITCH + (lid >> 4) * 16);
    const uint32_t b_base = (uint32_t)((warp_n * 32 + ((lid >> 4) * 8) + (lid & 7)) * PITCH +
                                       ((lid >> 3) & 1) * 16);

    float acc[4][4][4];
#pragma unroll
    for (int mi = 0; mi < 4; mi++)
#pragma unroll
        for (int ni = 0; ni < 4; ni++)
#pragma unroll
            for (int q = 0; q < 4; q++) acc[mi][ni][q] = 0.f;

    // issue chunk c into stage c%NST
    auto issue = [&](int c) {
        const uint32_t st = sb + (uint32_t)(c % NST) * STAGEB;
        const int k0 = c * KC;
#pragma unroll
        for (int o = 0; o < 4; o++) {
            cp16(st + o * OPB + r0i * PITCH + s0i * 16, gOp[o] + (size_t)r0i * D_ + k0 + s0i * 8);
            cp16(st + o * OPB + r1i * PITCH + s1i * 16, gOp[o] + (size_t)r1i * D_ + k0 + s1i * 8);
        }
    };

    issue(0); CP_COMMIT();
    issue(1); CP_COMMIT();

    for (int c = 0; c < D_ / KC; c++) {
        CP_WAIT(1);
        __syncthreads();
        if (c + 2 < D_ / KC) issue(c + 2);
        CP_COMMIT();

        const uint32_t st = sb + (uint32_t)(c % NST) * STAGEB;
        const uint32_t sAh = st;
        const uint32_t sAl = st + OPB;
        const uint32_t sBh = st + 2 * OPB;
        const uint32_t sBl = st + 3 * OPB;

#pragma unroll
        for (int ks = 0; ks < 2; ks++) {
            const uint32_t kb = ks * 32;
            uint32_t ah[4][4], al[4][4], bh[4][2], bl[4][2];
#pragma unroll
            for (int mi = 0; mi < 4; mi++) {
                const uint32_t ao = a_base + mi * 16 * PITCH + kb;
                ldm_x4(sAh + ao, ah[mi][0], ah[mi][1], ah[mi][2], ah[mi][3]);
                ldm_x4(sAl + ao, al[mi][0], al[mi][1], al[mi][2], al[mi][3]);
            }
#pragma unroll
            for (int p = 0; p < 2; p++) {
                const uint32_t bo = b_base + p * 16 * PITCH + kb;
                ldm_x4(sBh + bo, bh[2 * p][0], bh[2 * p][1], bh[2 * p + 1][0], bh[2 * p + 1][1]);
                ldm_x4(sBl + bo, bl[2 * p][0], bl[2 * p][1], bl[2 * p + 1][0], bl[2 * p + 1][1]);
            }
#pragma unroll
            for (int mi = 0; mi < 4; mi++)
#pragma unroll
                for (int ni = 0; ni < 4; ni++) {
                    mma_bf16(acc[mi][ni], ah[mi], bh[ni]);
                    mma_bf16(acc[mi][ni], ah[mi], bl[ni]);
                    mma_bf16(acc[mi][ni], al[mi], bh[ni]);
                }
        }
    }

    const int g = lid >> 2, tg = lid & 3;
#pragma unroll
    for (int mi = 0; mi < 4; mi++) {
#pragma unroll
        for (int ni = 0; ni < 4; ni++) {
            const int row = row0 + warp_m * 64 + mi * 16 + g;
            const int col = col0 + warp_n * 32 + ni * 8 + tg * 2;
            float2 v0 = {acc[mi][ni][0], acc[mi][ni][1]};
            float2 v1 = {acc[mi][ni][2], acc[mi][ni][3]};
            *(float2*)(C + (size_t)row * D_ + col) = v0;
            *(float2*)(C + (size_t)(row + 8) * D_ + col) = v1;
        }
    }
}

// ------------------------- FAVOR+ feature map (tiled, fused) ----------------
// MODE 0 (queries): raw xd kept in registers across all 3 m-chunks; per-row max
//                   + diag applied in-kernel; writes FINAL qf once.
// MODE 1 (keys):    writes raw xd, per-row max and diag to gmem (global max
//                   stabilizer resolved later; exp fused into consumers).
#define FEAT_SMEM ((64 * 65 + 128 * 65 + 64) * 4)

template <int MODE>
__global__ __launch_bounds__(256) void feat_kernel(const float* __restrict__ QK,
                                                   const float* __restrict__ proj,
                                                   float* __restrict__ fout,
                                                   float* __restrict__ diag_out,
                                                   float* __restrict__ rowmax_out) {
    const int bh = blockIdx.y;
    const int n0 = blockIdx.x * 64;
    const int b = bh >> 4, h = bh & 15;
    const int t = threadIdx.x;
    const int lane = t & 31;
    const int tr = t >> 5;
    extern __shared__ float fsm[];
    float* xst = fsm;                    // [64][65] transposed x
    float* prs = fsm + 64 * 65;          // [128][65] proj chunk
    float* diag_s = fsm + 64 * 65 + 128 * 65;  // [64]
    const size_t idx0 = (size_t)bh * N_ + n0;

#pragma unroll
    for (int p4 = 0; p4 < 4; p4++) {
        const int f4 = t + p4 * 256;
        const int r = f4 >> 4;
        const int kq = (f4 & 15) * 4;
        float4 v = *(const float4*)(QK + ((size_t)(b * N_ + n0 + r)) * D_ + h * 64 + kq);
        xst[(kq + 0) * 65 + r] = v.x * DN_;
        xst[(kq + 1) * 65 + r] = v.y * DN_;
        xst[(kq + 2) * 65 + r] = v.z * DN_;
        xst[(kq + 3) * 65 + r] = v.w * DN_;
    }
    __syncthreads();

    if (t < 64) {
        float s = 0.f;
#pragma unroll 16
        for (int k = 0; k < 64; k++) {
            const float v = xst[k * 65 + t];
            s += v * v;
        }
        diag_s[t] = 0.5f * s;
        if (MODE == 1) diag_out[idx0 + t] = 0.5f * s;
    }

    float acc[3][8][4];
#pragma unroll
    for (int p = 0; p < 3; p++)
#pragma unroll
        for (int j = 0; j < 8; j++)
#pragma unroll
            for (int jm = 0; jm < 4; jm++) acc[p][j][jm] = 0.f;

#pragma unroll
    for (int p = 0; p < 3; p++) {
        __syncthreads();
#pragma unroll
        for (int p4 = 0; p4 < 8; p4++) {
            const int f4 = t + p4 * 256;
            const int mm = f4 >> 4;
            const int kq = (f4 & 15) * 4;
            int gm = p * 128 + mm;
            if (gm > M_ - 1) gm = M_ - 1;
            float4 v = *(const float4*)(proj + (size_t)gm * 64 + kq);
            prs[mm * 65 + kq + 0] = v.x;
            prs[mm * 65 + kq + 1] = v.y;
            prs[mm * 65 + kq + 2] = v.z;
            prs[mm * 65 + kq + 3] = v.w;
        }
        __syncthreads();

#pragma unroll 8
        for (int k = 0; k < 64; k++) {
            float xv[8], pv[4];
#pragma unroll
            for (int j = 0; j < 8; j++) xv[j] = xst[k * 65 + tr * 8 + j];
#pragma unroll
            for (int jm = 0; jm < 4; jm++) pv[jm] = prs[(lane + 32 * jm) * 65 + k];
#pragma unroll
            for (int j = 0; j < 8; j++)
#pragma unroll
                for (int jm = 0; jm < 4; jm++) acc[p][j][jm] += xv[j] * pv[jm];
        }
    }

    // per-row max over valid m
    float lmax[8];
#pragma unroll
    for (int j = 0; j < 8; j++) lmax[j] = -1e30f;
#pragma unroll
    for (int p = 0; p < 3; p++)
#pragma unroll
        for (int jm = 0; jm < 4; jm++) {
            const int m = p * 128 + lane + 32 * jm;
            if (m < M_)
#pragma unroll
                for (int j = 0; j < 8; j++) lmax[j] = fmaxf(lmax[j], acc[p][j][jm]);
        }
#pragma unroll
    for (int off = 16; off > 0; off >>= 1)
#pragma unroll
        for (int j = 0; j < 8; j++)
            lmax[j] = fmaxf(lmax[j], __shfl_xor_sync(0xffffffffu, lmax[j], off));

    if (MODE == 0) {
        float sub[8];
#pragma unroll
        for (int j = 0; j < 8; j++) sub[j] = diag_s[tr * 8 + j] + lmax[j];
#pragma unroll
        for (int p = 0; p < 3; p++)
#pragma unroll
            for (int jm = 0; jm < 4; jm++) {
                const int m = p * 128 + lane + 32 * jm;
                if (m < M_)
#pragma unroll
                    for (int j = 0; j < 8; j++)
                        fout[(idx0 + tr * 8 + j) * M_ + m] =
                            RATIO_ * (expf(acc[p][j][jm] - sub[j]) + EPS_F);
            }
    } else {
#pragma unroll
        for (int p = 0; p < 3; p++)
#pragma unroll
            for (int jm = 0; jm < 4; jm++) {
                const int m = p * 128 + lane + 32 * jm;
                if (m < M_)
#pragma unroll
                    for (int j = 0; j < 8; j++)
                        fout[(idx0 + tr * 8 + j) * M_ + m] = acc[p][j][jm];
            }
        if (lane == 0) {
#pragma unroll
            for (int j = 0; j < 8; j++) rowmax_out[idx0 + tr * 8 + j] = lmax[j];
        }
    }
}

__global__ __launch_bounds__(256) void kmax_reduce_kernel(const float* __restrict__ rowmax,
                                                          float* __restrict__ kmax) {
    __shared__ float sm[256];
    const int bh = blockIdx.x;
    float v = -1e30f;
    for (int i = threadIdx.x; i < N_; i += 256)
        v = fmaxf(v, rowmax[bh * N_ + i]);
    sm[threadIdx.x] = v;
    __syncthreads();
#pragma unroll
    for (int off = 128; off > 0; off >>= 1) {
        if (threadIdx.x < off) sm[threadIdx.x] = fmaxf(sm[threadIdx.x], sm[threadIdx.x + off]);
        __syncthreads();
    }
    if (threadIdx.x == 0) kmax[bh] = sm[0];
}

// ------------------------- linear attention ---------------------------------
// two-stage ksum with fused exp (reads raw kf)
__global__ __launch_bounds__(288) void ksum_part_kernel(const float* __restrict__ kf,
                                                        const float* __restrict__ kdiag,
                                                        const float* __restrict__ kmax,
                                                        float* __restrict__ part) {
    const int bh = blockIdx.y;
    const int c = blockIdx.x;
    const int m = threadIdx.x;
    if (m >= M_) return;
    const float km = kmax[bh];
    float s = 0.f;
    const float* base = kf + ((size_t)bh * N_ + c * 256) * M_ + m;
    const float* kd = kdiag + (size_t)bh * N_ + c * 256;
    for (int n = 0; n < 256; n++)
        s += RATIO_ * (expf(base[(size_t)n * M_] - kd[n] - km) + EPS_F);
    part[((size_t)bh * 16 + c) * 272 + m] = s;
}

__global__ __launch_bounds__(288) void ksum_final_kernel(const float* __restrict__ part,
                                                         float* __restrict__ ksum) {
    const int bh = blockIdx.x;
    const int m = threadIdx.x;
    if (m >= M_) return;
    float s = 0.f;
#pragma unroll
    for (int c = 0; c < 16; c++) s += part[((size_t)bh * 16 + c) * 272 + m];
    ksum[bh * M_ + m] = s;
}

// ctx[bh][m][d] = sum_n kf_final[bh][n][m] * V[b][n][h*64+d]  (exp fused at fill)
__global__ __launch_bounds__(256) void ctx_kernel(const float* __restrict__ kf,
                                                  const float* __restrict__ V,
                                                  const float* __restrict__ kdiag,
                                                  const float* __restrict__ kmax,
                                                  float* __restrict__ ctx) {
    __shared__ float Ks[32][32];
    __shared__ float Vs[32][64];

    const int bh = blockIdx.y;
    const int b = bh >> 4, h = bh & 15;
    const int m0 = blockIdx.x * 32;
    const int t = threadIdx.x;
    const int d = t & 63;
    const int mb = (t >> 6) * 8;
    const float km = kmax[bh];

    float acc[8];
#pragma unroll
    for (int j = 0; j < 8; j++) acc[j] = 0.f;

    for (int n0 = 0; n0 < N_; n0 += 32) {
#pragma unroll
        for (int q = 0; q < 4; q++) {
            const int idx = t + q * 256;
            const int i = idx >> 5, j = idx & 31;
            const int m = m0 + j;
            float val = 0.f;
            if (m < M_) {
                const float raw = kf[((size_t)(bh * N_ + n0 + i)) * M_ + m];
                val = RATIO_ * (expf(raw - kdiag[(size_t)bh * N_ + n0 + i] - km) + EPS_F);
            }
            Ks[i][j] = val;
        }
#pragma unroll
        for (int q = 0; q < 8; q++) {
            const int idx = t + q * 256;
            const int i = idx >> 6, dd = idx & 63;
            Vs[i][dd] = V[((size_t)(b * N_ + n0 + i)) * D_ + h * 64 + dd];
        }
        __syncthreads();
#pragma unroll 8
        for (int i = 0; i < 32; i++) {
            const float vv = Vs[i][d];
#pragma unroll
            for (int j = 0; j < 8; j++) acc[j] += Ks[i][mb + j] * vv;
        }
        __syncthreads();
    }

#pragma unroll
    for (int j = 0; j < 8; j++) {
        const int m = m0 + mb + j;
        if (m < M_) ctx[((size_t)bh * M_ + m) * 64 + d] = acc[j];
    }
}

// out = (qf @ ctx) * dinv, dinv computed in-kernel from ksum; writes split bf16
__global__ __launch_bounds__(256) void attn_out_kernel(const float* __restrict__ qf,
                                                       const float* __restrict__ ctx,
                                                       const float* __restrict__ ksum,
                                                       __nv_bfloat16* __restrict__ ah,
                                                       __nv_bfloat16* __restrict__ al) {
    __shared__ float Cs[64][64];
    __shared__ float Qs[16][64];
    __shared__ float kss[320];
    __shared__ float red[8][4];

    const int bh = blockIdx.y;
    const int b = bh >> 4, h = bh & 15;
    const int n0 = blockIdx.x * 16;
    const int t = threadIdx.x;
    const int d = t & 63;
    const int rgidx = t >> 6;          // 0..3 row group
    const int rg = rgidx * 4;
    const int wid = t >> 5;
    const int lane = t & 31;

    for (int i = t; i < 320; i += 256) kss[i] = (i < M_) ? ksum[bh * M_ + i] : 0.f;

    float acc[4] = {0.f, 0.f, 0.f, 0.f};
    float dot[4] = {0.f, 0.f, 0.f, 0.f};

    for (int c = 0; c < 5; c++) {
        const int m0 = c * 64;
        const int mw = (M_ - m0 < 64) ? (M_ - m0) : 64;
#pragma unroll
        for (int q = 0; q < 16; q++) {
            const int idx = t + q * 256;
            const int mm = idx >> 6, dd = idx & 63;
            Cs[mm][dd] = (mm < mw) ? ctx[((size_t)bh * M_ + m0 + mm) * 64 + dd] : 0.f;
        }
#pragma unroll
        for (int q = 0; q < 4; q++) {
            const int idx = t + q * 256;
            const int r = idx >> 6, mm = idx & 63;
            Qs[r][mm] = (mm < mw) ? qf[((size_t)(bh * N_ + n0 + r)) * M_ + m0 + mm] : 0.f;
        }
        __syncthreads();

        // partial denominator: thread handles mm == d of this chunk
        const float ks_v = kss[m0 + d];
#pragma unroll
        for (int ii = 0; ii < 4; ii++) dot[ii] += Qs[rg + ii][d] * ks_v;

#pragma unroll 8
        for (int mm = 0; mm < 64; mm++) {
            const float cv = Cs[mm][d];
#pragma unroll
            for (int ii = 0; ii < 4; ii++) acc[ii] += Qs[rg + ii][mm] * cv;
        }
        __syncthreads();
    }

    // reduce dot over the 64 threads (2 warps) of this row group
#pragma unroll
    for (int off = 16; off > 0; off >>= 1)
#pragma unroll
        for (int ii = 0; ii < 4; ii++) dot[ii] += __shfl_xor_sync(0xffffffffu, dot[ii], off);
    if (lane == 0) {
#pragma unroll
        for (int ii = 0; ii < 4; ii++) red[wid][ii] = dot[ii];
    }
    __syncthreads();

#pragma unroll
    for (int ii = 0; ii < 4; ii++) {
        const float denom = red[2 * rgidx][ii] + red[2 * rgidx + 1][ii];
        const float v = acc[ii] / denom;
        const int n = n0 + rg + ii;
        const size_t o = ((size_t)(b * N_ + n)) * D_ + h * 64 + d;
        __nv_bfloat16 hv = __float2bfloat16(v);
        ah[o] = hv;
        al[o] = __float2bfloat16(v - __bfloat162float(hv));
    }
}

// ------------------------- residual + LayerNorm -----------------------------
__global__ __launch_bounds__(256) void ln_kernel(const float* __restrict__ x,
                                                 const float* __restrict__ o2,
                                                 const float* __restrict__ bo,
                                                 const float* __restrict__ gamma,
                                                 const float* __restrict__ beta,
                                                 float* __restrict__ out) {
    __shared__ float ss[256];
    __shared__ float sq[256];
    const int row = blockIdx.x;
    const int t = threadIdx.x;
    const size_t base = (size_t)row * D_;

    float yv[4];
    float s = 0.f, q = 0.f;
#pragma unroll
    for (int i = 0; i < 4; i++) {
        const int c = t + i * 256;
        const float v = x[base + c] + o2[base + c] + bo[c];
        yv[i] = v;
        s += v;
        q += v * v;
    }
    ss[t] = s;
    sq[t] = q;
    __syncthreads();
#pragma unroll
    for (int off = 128; off > 0; off >>= 1) {
        if (t < off) { ss[t] += ss[t + off]; sq[t] += sq[t + off]; }
        __syncthreads();
    }
    const float mu = ss[0] * (1.f / (float)D_);
    const float var = sq[0] * (1.f / (float)D_) - mu * mu;
    const float rstd = rsqrtf(var + EPS_LN);
#pragma unroll
    for (int i = 0; i < 4; i++) {
        const int c = t + i * 256;
        out[base + c] = (yv[i] - mu) * rstd * gamma[c] + beta[c];
    }
}

// ------------------------- launch --------------------------------------------
extern "C" void kernel_launch(void* const* d_in, const int* in_sizes, int n_in,
                              void* d_out, int out_size) {
    const float* x     = (const float*)d_in[0];
    const float* Wq    = (const float*)d_in[1];
    const float* Wk    = (const float*)d_in[2];
    const float* Wv    = (const float*)d_in[3];
    const float* Wo    = (const float*)d_in[4];
    const float* bo    = (const float*)d_in[5];
    const float* proj  = (const float*)d_in[6];
    const float* gamma = (const float*)d_in[7];
    const float* beta  = (const float*)d_in[8];
    float* out = (float*)d_out;

    float *pQ, *pK, *pV, *pqf, *pkf, *pkd, *prm, *pkm, *pks, *pksp, *pctx, *po2;
    __nv_bfloat16 *pxh, *pxl, *pah, *pal, *pWth, *pWtl;
    cudaGetSymbolAddress((void**)&pQ,   g_Q);
    cudaGetSymbolAddress((void**)&pK,   g_K);
    cudaGetSymbolAddress((void**)&pV,   g_V);
    cudaGetSymbolAddress((void**)&pqf,  g_qf);
    cudaGetSymbolAddress((void**)&pkf,  g_kf);
    cudaGetSymbolAddress((void**)&pkd,  g_kdiag);
    cudaGetSymbolAddress((void**)&prm,  g_krowmax);
    cudaGetSymbolAddress((void**)&pkm,  g_kmax);
    cudaGetSymbolAddress((void**)&pks,  g_ksum);
    cudaGetSymbolAddress((void**)&pksp, g_ksum_part);
    cudaGetSymbolAddress((void**)&pctx, g_ctx);
    cudaGetSymbolAddress((void**)&po2,  g_out2);
    cudaGetSymbolAddress((void**)&pxh,  g_xh);
    cudaGetSymbolAddress((void**)&pxl,  g_xl);
    cudaGetSymbolAddress((void**)&pah,  g_ah);
    cudaGetSymbolAddress((void**)&pal,  g_al);
    cudaGetSymbolAddress((void**)&pWth, g_Wth);
    cudaGetSymbolAddress((void**)&pWtl, g_Wtl);

    cudaFuncSetAttribute(gemm_bf16x3, cudaFuncAttributeMaxDynamicSharedMemorySize, GSMEM);
    cudaFuncSetAttribute(feat_kernel<0>, cudaFuncAttributeMaxDynamicSharedMemorySize, FEAT_SMEM);
    cudaFuncSetAttribute(feat_kernel<1>, cudaFuncAttributeMaxDynamicSharedMemorySize, FEAT_SMEM);

    const size_t WSZ = (size_t)D_ * D_;

    // 0. operand prep
    split_x_kernel<<<BN_ * D_ / (256 * 4), 256>>>(x, pxh, pxl);
    splitT_W_kernel<<<dim3(32, 32), dim3(32, 32)>>>(Wq, pWth + 0 * WSZ, pWtl + 0 * WSZ);
    splitT_W_kernel<<<dim3(32, 32), dim3(32, 32)>>>(Wk, pWth + 1 * WSZ, pWtl + 1 * WSZ);
    splitT_W_kernel<<<dim3(32, 32), dim3(32, 32)>>>(Wv, pWth + 2 * WSZ, pWtl + 2 * WSZ);
    splitT_W_kernel<<<dim3(32, 32), dim3(32, 32)>>>(Wo, pWth + 3 * WSZ, pWtl + 3 * WSZ);

    dim3 gemmGrid(D_ / 128, BN_ / 128);

    // 1. QKV projections
    gemm_bf16x3<<<gemmGrid, 256, GSMEM>>>(pxh, pxl, pWth + 0 * WSZ, pWtl + 0 * WSZ, pQ);
    gemm_bf16x3<<<gemmGrid, 256, GSMEM>>>(pxh, pxl, pWth + 1 * WSZ, pWtl + 1 * WSZ, pK);
    gemm_bf16x3<<<gemmGrid, 256, GSMEM>>>(pxh, pxl, pWth + 2 * WSZ, pWtl + 2 * WSZ, pV);

    // 2. FAVOR+ features (Q fully fused; K raw + rowmax/diag)
    dim3 featGrid(N_ / 64, B_ * H_);
    feat_kernel<0><<<featGrid, 256, FEAT_SMEM>>>(pQ, proj, pqf, nullptr, nullptr);
    feat_kernel<1><<<featGrid, 256, FEAT_SMEM>>>(pK, proj, pkf, pkd, prm);
    kmax_reduce_kernel<<<B_ * H_, 256>>>(prm, pkm);

    // 3. Linear attention (exp fused into kf consumers; dinv fused into attn_out)
    ksum_part_kernel<<<dim3(16, B_ * H_), 288>>>(pkf, pkd, pkm, pksp);
    ksum_final_kernel<<<B_ * H_, 288>>>(pksp, pks);
    ctx_kernel<<<dim3(9, B_ * H_), 256>>>(pkf, pV, pkd, pkm, pctx);
    attn_out_kernel<<<dim3(N_ / 16, B_ * H_), 256>>>(pqf, pctx, pks, pah, pal);

    // 4. Output projection + residual + LayerNorm
    gemm_bf16x3<<<gemmGrid, 256, GSMEM>>>(pah, pal, pWth + 3 * WSZ, pWtl + 3 * WSZ, po2);
    ln_kernel<<<BN_, 256>>>(x, po2, bo, gamma, beta, out);
}

// round 6
// speedup vs baseline: 14.1667x; 1.3144x over previous
#include <cuda_runtime.h>
#include <cuda_bf16.h>
#include <cstdint>
#include <cstddef>

// Problem constants
#define B_  4
#define N_  4096
#define H_  16
#define DH_ 64
#define M_  266
#define D_  1024
#define ROWS_ (B_*H_*N_)        // 262144
#define BN_   (B_*N_)           // 16384
#define MP_ 288                 // padded feature count (m), zeros above 266
#define DP_ 80                  // padded head dim: 64 data + ones col (64) + zeros

#define DN_    0.3535533906f    // 64^-0.25
#define RATIO_ 0.0613139315f    // 266^-0.5
#define EPS_F  1e-4f
#define EPS_LN 1e-5f

// ------------------------- scratch (device globals) -------------------------
__device__ float g_Q[(size_t)BN_ * D_];
__device__ float g_K[(size_t)BN_ * D_];
__device__ float g_V[(size_t)BN_ * D_];
__device__ float g_kf[(size_t)ROWS_ * M_];       // raw xd for keys
__device__ float g_kdiag[ROWS_];
__device__ float g_krowmax[ROWS_];
__device__ float g_kmax[B_ * H_];
__device__ float g_out2[(size_t)BN_ * D_];

__device__ __nv_bfloat16 g_qfh[(size_t)ROWS_ * MP_];
__device__ __nv_bfloat16 g_qfl[(size_t)ROWS_ * MP_];
__device__ __nv_bfloat16 g_kTh[(size_t)B_ * H_ * MP_ * N_];   // kf^T [bh][m][n]
__device__ __nv_bfloat16 g_kTl[(size_t)B_ * H_ * MP_ * N_];
__device__ __nv_bfloat16 g_vTh[(size_t)B_ * H_ * DP_ * N_];   // V^T  [bh][d][n]
__device__ __nv_bfloat16 g_vTl[(size_t)B_ * H_ * DP_ * N_];
__device__ __nv_bfloat16 g_cTh[(size_t)B_ * H_ * DP_ * MP_];  // ctx^T [bh][d][m]
__device__ __nv_bfloat16 g_cTl[(size_t)B_ * H_ * DP_ * MP_];

__device__ __nv_bfloat16 g_xh[(size_t)BN_ * D_];
__device__ __nv_bfloat16 g_xl[(size_t)BN_ * D_];
__device__ __nv_bfloat16 g_ah[(size_t)BN_ * D_];
__device__ __nv_bfloat16 g_al[(size_t)BN_ * D_];
__device__ __nv_bfloat16 g_Wth[4][(size_t)D_ * D_];
__device__ __nv_bfloat16 g_Wtl[4][(size_t)D_ * D_];

// ------------------------- helpers ------------------------------------------
__device__ __forceinline__ uint32_t smem_u32(const void* p) {
    uint32_t a;
    asm("{ .reg .u64 t; cvta.to.shared.u64 t, %1; cvt.u32.u64 %0, t; }" : "=r"(a) : "l"(p));
    return a;
}
__device__ __forceinline__ void ldm_x4(uint32_t addr, uint32_t& r0, uint32_t& r1,
                                       uint32_t& r2, uint32_t& r3) {
    asm volatile("ldmatrix.sync.aligned.m8n8.x4.shared.b16 {%0,%1,%2,%3}, [%4];"
                 : "=r"(r0), "=r"(r1), "=r"(r2), "=r"(r3) : "r"(addr));
}
__device__ __forceinline__ void mma_bf16(float* c, const uint32_t* a, const uint32_t* b) {
    asm volatile(
        "mma.sync.aligned.m16n8k16.row.col.f32.bf16.bf16.f32 "
        "{%0,%1,%2,%3}, {%4,%5,%6,%7}, {%8,%9}, {%0,%1,%2,%3};"
        : "+f"(c[0]), "+f"(c[1]), "+f"(c[2]), "+f"(c[3])
        : "r"(a[0]), "r"(a[1]), "r"(a[2]), "r"(a[3]), "r"(b[0]), "r"(b[1]));
}
__device__ __forceinline__ void cp16(uint32_t saddr, const void* gptr) {
    asm volatile("cp.async.cg.shared.global [%0], [%1], 16;" :: "r"(saddr), "l"(gptr));
}
#define CP_COMMIT() asm volatile("cp.async.commit_group;" ::: "memory")
#define CP_WAIT(n)  asm volatile("cp.async.wait_group %0;" :: "n"(n) : "memory")

__device__ __forceinline__ uint32_t pack_bf16x2(float a, float b) {
    __nv_bfloat162 t;
    t.x = __float2bfloat16(a);
    t.y = __float2bfloat16(b);
    return *reinterpret_cast<uint32_t*>(&t);
}

// ------------------------- split / transpose kernels ------------------------
__global__ __launch_bounds__(256) void split_x_kernel(const float* __restrict__ x,
                                                      __nv_bfloat16* __restrict__ xh,
                                                      __nv_bfloat16* __restrict__ xl) {
    const size_t i = ((size_t)blockIdx.x * 256 + threadIdx.x) * 4;
    float4 v = *(const float4*)(x + i);
    float a[4] = {v.x, v.y, v.z, v.w};
#pragma unroll
    for (int j = 0; j < 4; j++) {
        __nv_bfloat16 h = __float2bfloat16(a[j]);
        xh[i + j] = h;
        xl[i + j] = __float2bfloat16(a[j] - __bfloat162float(h));
    }
}

__global__ __launch_bounds__(1024) void splitT_W_kernel(const float* __restrict__ W,
                                                        __nv_bfloat16* __restrict__ Th,
                                                        __nv_bfloat16* __restrict__ Tl) {
    __shared__ float tile[32][33];
    const int n = blockIdx.x * 32 + threadIdx.x;
    const int k = blockIdx.y * 32 + threadIdx.y;
    tile[threadIdx.y][threadIdx.x] = W[(size_t)k * D_ + n];
    __syncthreads();
    const float v = tile[threadIdx.x][threadIdx.y];
    const int on = blockIdx.x * 32 + threadIdx.y;
    const int ok = blockIdx.y * 32 + threadIdx.x;
    __nv_bfloat16 h = __float2bfloat16(v);
    Th[(size_t)on * D_ + ok] = h;
    Tl[(size_t)on * D_ + ok] = __float2bfloat16(v - __bfloat162float(h));
}

// ------------------------- mma.sync bf16-split GEMM (KC=64, 3-stage) --------
#define KC    64
#define PITCH 144                   // 128B data + 16 pad
#define OPB   (128 * PITCH)         // 18432
#define STAGEB (4 * OPB)            // 73728
#define NST   3
#define GSMEM (NST * STAGEB)        // 221184

__global__ __launch_bounds__(256, 1) void gemm_bf16x3(
    const __nv_bfloat16* __restrict__ Ah, const __nv_bfloat16* __restrict__ Al,
    const __nv_bfloat16* __restrict__ Bh, const __nv_bfloat16* __restrict__ Bl,
    float* __restrict__ C) {
    extern __shared__ char smem[];
    const uint32_t sb = smem_u32(smem);
    const int tid = threadIdx.x;
    const int wid = tid >> 5;
    const int lid = tid & 31;
    const int warp_m = wid & 1;
    const int warp_n = wid >> 1;
    const int row0 = blockIdx.y * 128;
    const int col0 = blockIdx.x * 128;

    const __nv_bfloat16* gOp[4] = {Ah + (size_t)row0 * D_, Al + (size_t)row0 * D_,
                                   Bh + (size_t)col0 * D_, Bl + (size_t)col0 * D_};

    const uint32_t a_base = (uint32_t)((warp_m * 64 + (lid & 15)) * PITCH + (lid >> 4) * 16);
    const uint32_t b_base = (uint32_t)((warp_n * 32 + ((lid >> 4) * 8) + (lid & 7)) * PITCH +
                                       ((lid >> 3) & 1) * 16);

    float acc[4][4][4];
#pragma unroll
    for (int mi = 0; mi < 4; mi++)
#pragma unroll
        for (int ni = 0; ni < 4; ni++)
#pragma unroll
            for (int q = 0; q < 4; q++) acc[mi][ni][q] = 0.f;

    auto issue = [&](int c) {
        const uint32_t st = sb + (uint32_t)(c % NST) * STAGEB;
        const int k0 = c * KC;
        for (int i = tid; i < 1024; i += 256) {
            const int r = i >> 3, cc = i & 7;
#pragma unroll
            for (int o = 0; o < 4; o++)
                cp16(st + o * OPB + r * PITCH + cc * 16, gOp[o] + (size_t)r * D_ + k0 + cc * 8);
        }
    };

    issue(0); CP_COMMIT();
    issue(1); CP_COMMIT();

    for (int c = 0; c < D_ / KC; c++) {
        CP_WAIT(1);
        __syncthreads();
        if (c + 2 < D_ / KC) issue(c + 2);
        CP_COMMIT();

        const uint32_t st = sb + (uint32_t)(c % NST) * STAGEB;
#pragma unroll
        for (int ks = 0; ks < 4; ks++) {
            const uint32_t kb = ks * 32;
            uint32_t ah[4][4], al[4][4], bh[4][2], bl[4][2];
#pragma unroll
            for (int mi = 0; mi < 4; mi++) {
                const uint32_t ao = a_base + mi * 16 * PITCH + kb;
                ldm_x4(st + ao, ah[mi][0], ah[mi][1], ah[mi][2], ah[mi][3]);
                ldm_x4(st + OPB + ao, al[mi][0], al[mi][1], al[mi][2], al[mi][3]);
            }
#pragma unroll
            for (int p = 0; p < 2; p++) {
                const uint32_t bo = b_base + p * 16 * PITCH + kb;
                ldm_x4(st + 2 * OPB + bo, bh[2 * p][0], bh[2 * p][1], bh[2 * p + 1][0], bh[2 * p + 1][1]);
                ldm_x4(st + 3 * OPB + bo, bl[2 * p][0], bl[2 * p][1], bl[2 * p + 1][0], bl[2 * p + 1][1]);
            }
#pragma unroll
            for (int mi = 0; mi < 4; mi++)
#pragma unroll
                for (int ni = 0; ni < 4; ni++) {
                    mma_bf16(acc[mi][ni], ah[mi], bh[ni]);
                    mma_bf16(acc[mi][ni], ah[mi], bl[ni]);
                    mma_bf16(acc[mi][ni], al[mi], bh[ni]);
                }
        }
    }

    const int g = lid >> 2, tg = lid & 3;
#pragma unroll
    for (int mi = 0; mi < 4; mi++) {
#pragma unroll
        for (int ni = 0; ni < 4; ni++) {
            const int row = row0 + warp_m * 64 + mi * 16 + g;
            const int col = col0 + warp_n * 32 + ni * 8 + tg * 2;
            float2 v0 = {acc[mi][ni][0], acc[mi][ni][1]};
            float2 v1 = {acc[mi][ni][2], acc[mi][ni][3]};
            *(float2*)(C + (size_t)row * D_ + col) = v0;
            *(float2*)(C + (size_t)(row + 8) * D_ + col) = v1;
        }
    }
}

// ------------------------- FAVOR+ feature map (tiled, fused) ----------------
// MODE 0 (queries): exp applied in-kernel; writes split-bf16 qf [row][MP_],
//                   zero-padded for m in [266,288).
// MODE 1 (keys):    raw xd fp32 [row][M_], diag + rowmax to gmem.
#define FEAT_SMEM ((64 * 65 + 128 * 65 + 64) * 4)

template <int MODE>
__global__ __launch_bounds__(256) void feat_kernel(const float* __restrict__ QK,
                                                   const float* __restrict__ proj,
                                                   float* __restrict__ fout,
                                                   __nv_bfloat16* __restrict__ fh,
                                                   __nv_bfloat16* __restrict__ fl,
                                                   float* __restrict__ diag_out,
                                                   float* __restrict__ rowmax_out) {
    const int bh = blockIdx.y;
    const int n0 = blockIdx.x * 64;
    const int b = bh >> 4, h = bh & 15;
    const int t = threadIdx.x;
    const int lane = t & 31;
    const int tr = t >> 5;
    extern __shared__ float fsm[];
    float* xst = fsm;
    float* prs = fsm + 64 * 65;
    float* diag_s = fsm + 64 * 65 + 128 * 65;
    const size_t idx0 = (size_t)bh * N_ + n0;

#pragma unroll
    for (int p4 = 0; p4 < 4; p4++) {
        const int f4 = t + p4 * 256;
        const int r = f4 >> 4;
        const int kq = (f4 & 15) * 4;
        float4 v = *(const float4*)(QK + ((size_t)(b * N_ + n0 + r)) * D_ + h * 64 + kq);
        xst[(kq + 0) * 65 + r] = v.x * DN_;
        xst[(kq + 1) * 65 + r] = v.y * DN_;
        xst[(kq + 2) * 65 + r] = v.z * DN_;
        xst[(kq + 3) * 65 + r] = v.w * DN_;
    }
    __syncthreads();

    if (t < 64) {
        float s = 0.f;
#pragma unroll 16
        for (int k = 0; k < 64; k++) {
            const float v = xst[k * 65 + t];
            s += v * v;
        }
        diag_s[t] = 0.5f * s;
        if (MODE == 1) diag_out[idx0 + t] = 0.5f * s;
    }

    float acc[3][8][4];
#pragma unroll
    for (int p = 0; p < 3; p++)
#pragma unroll
        for (int j = 0; j < 8; j++)
#pragma unroll
            for (int jm = 0; jm < 4; jm++) acc[p][j][jm] = 0.f;

#pragma unroll
    for (int p = 0; p < 3; p++) {
        __syncthreads();
#pragma unroll
        for (int p4 = 0; p4 < 8; p4++) {
            const int f4 = t + p4 * 256;
            const int mm = f4 >> 4;
            const int kq = (f4 & 15) * 4;
            int gm = p * 128 + mm;
            if (gm > M_ - 1) gm = M_ - 1;
            float4 v = *(const float4*)(proj + (size_t)gm * 64 + kq);
            prs[mm * 65 + kq + 0] = v.x;
            prs[mm * 65 + kq + 1] = v.y;
            prs[mm * 65 + kq + 2] = v.z;
            prs[mm * 65 + kq + 3] = v.w;
        }
        __syncthreads();

#pragma unroll 8
        for (int k = 0; k < 64; k++) {
            float xv[8], pv[4];
#pragma unroll
            for (int j = 0; j < 8; j++) xv[j] = xst[k * 65 + tr * 8 + j];
#pragma unroll
            for (int jm = 0; jm < 4; jm++) pv[jm] = prs[(lane + 32 * jm) * 65 + k];
#pragma unroll
            for (int j = 0; j < 8; j++)
#pragma unroll
                for (int jm = 0; jm < 4; jm++) acc[p][j][jm] += xv[j] * pv[jm];
        }
    }

    float lmax[8];
#pragma unroll
    for (int j = 0; j < 8; j++) lmax[j] = -1e30f;
#pragma unroll
    for (int p = 0; p < 3; p++)
#pragma unroll
        for (int jm = 0; jm < 4; jm++) {
            const int m = p * 128 + lane + 32 * jm;
            if (m < M_)
#pragma unroll
                for (int j = 0; j < 8; j++) lmax[j] = fmaxf(lmax[j], acc[p][j][jm]);
        }
#pragma unroll
    for (int off = 16; off > 0; off >>= 1)
#pragma unroll
        for (int j = 0; j < 8; j++)
            lmax[j] = fmaxf(lmax[j], __shfl_xor_sync(0xffffffffu, lmax[j], off));

    if (MODE == 0) {
        float sub[8];
#pragma unroll
        for (int j = 0; j < 8; j++) sub[j] = diag_s[tr * 8 + j] + lmax[j];
#pragma unroll
        for (int p = 0; p < 3; p++)
#pragma unroll
            for (int jm = 0; jm < 4; jm++) {
                const int m = p * 128 + lane + 32 * jm;
                if (m < MP_) {
#pragma unroll
                    for (int j = 0; j < 8; j++) {
                        const float v = (m < M_)
                            ? RATIO_ * (expf(acc[p][j][jm] - sub[j]) + EPS_F) : 0.f;
                        const size_t o = (idx0 + tr * 8 + j) * MP_ + m;
                        __nv_bfloat16 hv = __float2bfloat16(v);
                        fh[o] = hv;
                        fl[o] = __float2bfloat16(v - __bfloat162float(hv));
                    }
                }
            }
    } else {
#pragma unroll
        for (int p = 0; p < 3; p++)
#pragma unroll
            for (int jm = 0; jm < 4; jm++) {
                const int m = p * 128 + lane + 32 * jm;
                if (m < M_)
#pragma unroll
                    for (int j = 0; j < 8; j++)
                        fout[(idx0 + tr * 8 + j) * M_ + m] = acc[p][j][jm];
            }
        if (lane == 0) {
#pragma unroll
            for (int j = 0; j < 8; j++) rowmax_out[idx0 + tr * 8 + j] = lmax[j];
        }
    }
}

__global__ __launch_bounds__(256) void kmax_reduce_kernel(const float* __restrict__ rowmax,
                                                          float* __restrict__ kmax) {
    __shared__ float sm[256];
    const int bh = blockIdx.x;
    float v = -1e30f;
    for (int i = threadIdx.x; i < N_; i += 256)
        v = fmaxf(v, rowmax[bh * N_ + i]);
    sm[threadIdx.x] = v;
    __syncthreads();
#pragma unroll
    for (int off = 128; off > 0; off >>= 1) {
        if (threadIdx.x < off) sm[threadIdx.x] = fmaxf(sm[threadIdx.x], sm[threadIdx.x + off]);
        __syncthreads();
    }
    if (threadIdx.x == 0) kmax[bh] = sm[0];
}

// kconvT: kf raw -> exp -> kf^T split bf16 [bh][m (288, zero-pad)][n]
__global__ __launch_bounds__(1024) void kconvT_kernel(const float* __restrict__ kf,
                                                      const float* __restrict__ kdiag,
                                                      const float* __restrict__ kmax,
                                                      __nv_bfloat16* __restrict__ kTh,
                                                      __nv_bfloat16* __restrict__ kTl) {
    __shared__ float sm[32][33];
    const int bh = blockIdx.z;
    const int m0 = blockIdx.x * 32;
    const int n0 = blockIdx.y * 32;
    const int tx = threadIdx.x, ty = threadIdx.y;
    const float km = kmax[bh];

    const int m = m0 + tx;
    const int n = n0 + ty;
    float v = 0.f;
    if (m < M_) {
        const float raw = kf[((size_t)bh * N_ + n) * M_ + m];
        v = RATIO_ * (expf(raw - kdiag[(size_t)bh * N_ + n] - km) + EPS_F);
    }
    sm[ty][tx] = v;
    __syncthreads();

    const float w = sm[tx][ty];
    const size_t o = ((size_t)bh * MP_ + m0 + ty) * N_ + n0 + tx;
    __nv_bfloat16 hv = __float2bfloat16(w);
    kTh[o] = hv;
    kTl[o] = __float2bfloat16(w - __bfloat162float(hv));
}

// vconvT: V fp32 -> V^T split bf16 [bh][d (80)][n]; row 64 = ones, 65..79 zero
__global__ __launch_bounds__(256) void vconvT_kernel(const float* __restrict__ V,
                                                     __nv_bfloat16* __restrict__ vTh,
                                                     __nv_bfloat16* __restrict__ vTl) {
    __shared__ float sm[64][33];
    const int bh = blockIdx.y;
    const int b = bh >> 4, h = bh & 15;
    const int n0 = blockIdx.x * 32;
    const int t = threadIdx.x;

#pragma unroll
    for (int q = 0; q < 8; q++) {
        const int idx = t + q * 256;
        const int d = idx & 63, j = idx >> 6;
        sm[d][j] = V[((size_t)(b * N_ + n0 + j)) * D_ + h * 64 + d];
    }
    __syncthreads();

#pragma unroll
    for (int q = 0; q < 10; q++) {
        const int idx = t + q * 256;
        const int j = idx & 31, dd = idx >> 5;
        const float v = (dd < 64) ? sm[dd][j] : ((dd == 64) ? 1.f : 0.f);
        const size_t o = ((size_t)bh * DP_ + dd) * N_ + n0 + j;
        __nv_bfloat16 hv = __float2bfloat16(v);
        vTh[o] = hv;
        vTl[o] = __float2bfloat16(v - __bfloat162float(hv));
    }
}

// ------------------------- ctx MMA: ctx^T = (kf^T @ V)^T --------------------
// C[m 96][d 80] per CTA; A = kfT [m][k=n], B = vT [d][k=n]; K = 4096.
#define CTX_PITCH 144
#define CTX_AOPB (96 * CTX_PITCH)    // 13824
#define CTX_BOPB (80 * CTX_PITCH)    // 11520
#define CTX_STAGE (2 * CTX_AOPB + 2 * CTX_BOPB)  // 50688
#define CTX_SMEM (3 * CTX_STAGE)     // 152064

__global__ __launch_bounds__(192, 1) void ctx_mma_kernel(
    const __nv_bfloat16* __restrict__ kTh, const __nv_bfloat16* __restrict__ kTl,
    const __nv_bfloat16* __restrict__ vTh, const __nv_bfloat16* __restrict__ vTl,
    __nv_bfloat16* __restrict__ cTh, __nv_bfloat16* __restrict__ cTl) {
    extern __shared__ char smem[];
    const uint32_t sb = smem_u32(smem);
    const int tid = threadIdx.x;
    const int wid = tid >> 5;     // 0..5, each warp owns m16 strip
    const int lid = tid & 31;
    const int bh = blockIdx.y;
    const int m0 = blockIdx.x * 96;

    const __nv_bfloat16* gA0 = kTh + ((size_t)bh * MP_ + m0) * N_;
    const __nv_bfloat16* gA1 = kTl + ((size_t)bh * MP_ + m0) * N_;
    const __nv_bfloat16* gB0 = vTh + (size_t)bh * DP_ * N_;
    const __nv_bfloat16* gB1 = vTl + (size_t)bh * DP_ * N_;

    const uint32_t a_base = (uint32_t)((wid * 16 + (lid & 15)) * CTX_PITCH + (lid >> 4) * 16);
    const uint32_t b_base = (uint32_t)((((lid >> 4) * 8) + (lid & 7)) * CTX_PITCH +
                                       ((lid >> 3) & 1) * 16);

    float acc[10][4];
#pragma unroll
    for (int t2 = 0; t2 < 10; t2++)
#pragma unroll
        for (int q = 0; q < 4; q++) acc[t2][q] = 0.f;

    auto issue = [&](int c) {
        const uint32_t st = sb + (uint32_t)(c % 3) * CTX_STAGE;
        const int k0 = c * 64;
        for (int i = tid; i < 768; i += 192) {
            const int r = i >> 3, cc = i & 7;
            cp16(st + r * CTX_PITCH + cc * 16, gA0 + (size_t)r * N_ + k0 + cc * 8);
            cp16(st + CTX_AOPB + r * CTX_PITCH + cc * 16, gA1 + (size_t)r * N_ + k0 + cc * 8);
        }
        for (int i = tid; i < 640; i += 192) {
            const int r = i >> 3, cc = i & 7;
            cp16(st + 2 * CTX_AOPB + r * CTX_PITCH + cc * 16, gB0 + (size_t)r * N_ + k0 + cc * 8);
            cp16(st + 2 * CTX_AOPB + CTX_BOPB + r * CTX_PITCH + cc * 16,
                 gB1 + (size_t)r * N_ + k0 + cc * 8);
        }
    };

    issue(0); CP_COMMIT();
    issue(1); CP_COMMIT();

    for (int c = 0; c < N_ / 64; c++) {
        CP_WAIT(1);
        __syncthreads();
        if (c + 2 < N_ / 64) issue(c + 2);
        CP_COMMIT();

        const uint32_t st = sb + (uint32_t)(c % 3) * CTX_STAGE;
#pragma unroll
        for (int ks = 0; ks < 4; ks++) {
            const uint32_t kb = ks * 32;
            uint32_t ah[4], al[4], bh2[10][2], bl2[10][2];
            ldm_x4(st + a_base + kb, ah[0], ah[1], ah[2], ah[3]);
            ldm_x4(st + CTX_AOPB + a_base + kb, al[0], al[1], al[2], al[3]);
#pragma unroll
            for (int p = 0; p < 5; p++) {
                const uint32_t bo = b_base + p * 16 * CTX_PITCH + kb;
                ldm_x4(st + 2 * CTX_AOPB + bo,
                       bh2[2 * p][0], bh2[2 * p][1], bh2[2 * p + 1][0], bh2[2 * p + 1][1]);
                ldm_x4(st + 2 * CTX_AOPB + CTX_BOPB + bo,
                       bl2[2 * p][0], bl2[2 * p][1], bl2[2 * p + 1][0], bl2[2 * p + 1][1]);
            }
#pragma unroll
            for (int t2 = 0; t2 < 10; t2++) {
                mma_bf16(acc[t2], ah, bh2[t2]);
                mma_bf16(acc[t2], ah, bl2[t2]);
                mma_bf16(acc[t2], al, bh2[t2]);
            }
        }
    }

    // epilogue: stage C [96 m][80 d] fp32 in smem, write ctx^T split bf16
    __syncthreads();
    float* sC = (float*)smem;
#pragma unroll
    for (int t2 = 0; t2 < 10; t2++) {
        const int r = lid >> 2;
        const int col = t2 * 8 + (lid & 3) * 2;
        sC[(wid * 16 + r) * 80 + col] = acc[t2][0];
        sC[(wid * 16 + r) * 80 + col + 1] = acc[t2][1];
        sC[(wid * 16 + r + 8) * 80 + col] = acc[t2][2];
        sC[(wid * 16 + r + 8) * 80 + col + 1] = acc[t2][3];
    }
    __syncthreads();
    for (int i = tid; i < 80 * 96; i += 192) {
        const int d = i / 96, m = i % 96;
        const float v = sC[m * 80 + d];
        const size_t o = ((size_t)bh * DP_ + d) * MP_ + m0 + m;
        __nv_bfloat16 hv = __float2bfloat16(v);
        cTh[o] = hv;
        cTl[o] = __float2bfloat16(v - __bfloat162float(hv));
    }
}

// ------------------------- attn MMA: out = (qf @ ctx) / denom ---------------
// C[n 128][d 80] per CTA; A = qf [n][k=m 288], B = ctxT [d][k=m]; denom = col 64.
#define AT_PITCH 112                 // 96B data + 16 pad
#define AT_AOPB (128 * AT_PITCH)     // 14336
#define AT_BOPB (80 * AT_PITCH)      // 8960
#define AT_STAGE (2 * AT_AOPB + 2 * AT_BOPB)  // 46592
#define AT_SMEM (3 * AT_STAGE)       // 139776

__global__ __launch_bounds__(256, 1) void attn_mma_kernel(
    const __nv_bfloat16* __restrict__ qfh, const __nv_bfloat16* __restrict__ qfl,
    const __nv_bfloat16* __restrict__ cTh, const __nv_bfloat16* __restrict__ cTl,
    __nv_bfloat16* __restrict__ ah_out, __nv_bfloat16* __restrict__ al_out) {
    extern __shared__ char smem[];
    const uint32_t sb = smem_u32(smem);
    const int tid = threadIdx.x;
    const int wid = tid >> 5;     // 0..7, each warp owns 16 n-rows
    const int lid = tid & 31;
    const int bh = blockIdx.y;
    const int b = bh >> 4, h = bh & 15;
    const int n0 = blockIdx.x * 128;

    const __nv_bfloat16* gA0 = qfh + (size_t)(bh * N_ + n0) * MP_;
    const __nv_bfloat16* gA1 = qfl + (size_t)(bh * N_ + n0) * MP_;
    const __nv_bfloat16* gB0 = cTh + (size_t)bh * DP_ * MP_;
    const __nv_bfloat16* gB1 = cTl + (size_t)bh * DP_ * MP_;

    const uint32_t a_base = (uint32_t)((wid * 16 + (lid & 15)) * AT_PITCH + (lid >> 4) * 16);
    const uint32_t b_base = (uint32_t)((((lid >> 4) * 8) + (lid & 7)) * AT_PITCH +
                                       ((lid >> 3) & 1) * 16);

    float acc[10][4];
#pragma unroll
    for (int t2 = 0; t2 < 10; t2++)
#pragma unroll
        for (int q = 0; q < 4; q++) acc[t2][q] = 0.f;

    auto issue = [&](int c) {
        const uint32_t st = sb + (uint32_t)(c % 3) * AT_STAGE;
        const int k0 = c * 48;
        for (int i = tid; i < 768; i += 256) {
            const int r = i / 6, cc = i % 6;
            cp16(st + r * AT_PITCH + cc * 16, gA0 + (size_t)r * MP_ + k0 + cc * 8);
            cp16(st + AT_AOPB + r * AT_PITCH + cc * 16, gA1 + (size_t)r * MP_ + k0 + cc * 8);
        }
        for (int i = tid; i < 480; i += 256) {
            const int r = i / 6, cc = i % 6;
            cp16(st + 2 * AT_AOPB + r * AT_PITCH + cc * 16, gB0 + (size_t)r * MP_ + k0 + cc * 8);
            cp16(st + 2 * AT_AOPB + AT_BOPB + r * AT_PITCH + cc * 16,
                 gB1 + (size_t)r * MP_ + k0 + cc * 8);
        }
    };

    issue(0); CP_COMMIT();
    issue(1); CP_COMMIT();

    for (int c = 0; c < MP_ / 48; c++) {      // 6 chunks
        CP_WAIT(1);
        __syncthreads();
        if (c + 2 < MP_ / 48) issue(c + 2);
        CP_COMMIT();

        const uint32_t st = sb + (uint32_t)(c % 3) * AT_STAGE;
#pragma unroll
        for (int ks = 0; ks < 3; ks++) {
            const uint32_t kb = ks * 32;
            uint32_t ah[4], al[4], bh2[10][2], bl2[10][2];
            ldm_x4(st + a_base + kb, ah[0], ah[1], ah[2], ah[3]);
            ldm_x4(st + AT_AOPB + a_base + kb, al[0], al[1], al[2], al[3]);
#pragma unroll
            for (int p = 0; p < 5; p++) {
                const uint32_t bo = b_base + p * 16 * AT_PITCH + kb;
                ldm_x4(st + 2 * AT_AOPB + bo,
                       bh2[2 * p][0], bh2[2 * p][1], bh2[2 * p + 1][0], bh2[2 * p + 1][1]);
                ldm_x4(st + 2 * AT_AOPB + AT_BOPB + bo,
                       bl2[2 * p][0], bl2[2 * p][1], bl2[2 * p + 1][0], bl2[2 * p + 1][1]);
            }
#pragma unroll
            for (int t2 = 0; t2 < 10; t2++) {
                mma_bf16(acc[t2], ah, bh2[t2]);
                mma_bf16(acc[t2], ah, bl2[t2]);
                mma_bf16(acc[t2], al, bh2[t2]);
            }
        }
    }

    // denom = accumulator column 64 (tile 8, col offset 0, lanes with lid%4==0)
    const float den0 = __shfl_sync(0xffffffffu, acc[8][0], lid & 28);
    const float den1 = __shfl_sync(0xffffffffu, acc[8][2], lid & 28);
    const float rd0 = 1.f / den0;
    const float rd1 = 1.f / den1;

    const int nr = n0 + wid * 16 + (lid >> 2);
    const size_t base0 = (size_t)(b * N_ + nr) * D_ + h * 64;
    const size_t base1 = (size_t)(b * N_ + nr + 8) * D_ + h * 64;
#pragma unroll
    for (int t2 = 0; t2 < 8; t2++) {
        const int d = t2 * 8 + (lid & 3) * 2;
        const float v0 = acc[t2][0] * rd0, v1 = acc[t2][1] * rd0;
        const float v2 = acc[t2][2] * rd1, v3 = acc[t2][3] * rd1;
        const __nv_bfloat16 h0 = __float2bfloat16(v0), h1 = __float2bfloat16(v1);
        const __nv_bfloat16 h2 = __float2bfloat16(v2), h3 = __float2bfloat16(v3);
        *(uint32_t*)(ah_out + base0 + d) = pack_bf16x2(v0, v1);
        *(uint32_t*)(al_out + base0 + d) =
            pack_bf16x2(v0 - __bfloat162float(h0), v1 - __bfloat162float(h1));
        *(uint32_t*)(ah_out + base1 + d) = pack_bf16x2(v2, v3);
        *(uint32_t*)(al_out + base1 + d) =
            pack_bf16x2(v2 - __bfloat162float(h2), v3 - __bfloat162float(h3));
    }
}

// ------------------------- residual + LayerNorm -----------------------------
__global__ __launch_bounds__(256) void ln_kernel(const float* __restrict__ x,
                                                 const float* __restrict__ o2,
                                                 const float* __restrict__ bo,
                                                 const float* __restrict__ gamma,
                                                 const float* __restrict__ beta,
                                                 float* __restrict__ out) {
    __shared__ float ss[256];
    __shared__ float sq[256];
    const int row = blockIdx.x;
    const int t = threadIdx.x;
    const size_t base = (size_t)row * D_;

    float yv[4];
    float s = 0.f, q = 0.f;
#pragma unroll
    for (int i = 0; i < 4; i++) {
        const int c = t + i * 256;
        const float v = x[base + c] + o2[base + c] + bo[c];
        yv[i] = v;
        s += v;
        q += v * v;
    }
    ss[t] = s;
    sq[t] = q;
    __syncthreads();
#pragma unroll
    for (int off = 128; off > 0; off >>= 1) {
        if (t < off) { ss[t] += ss[t + off]; sq[t] += sq[t + off]; }
        __syncthreads();
    }
    const float mu = ss[0] * (1.f / (float)D_);
    const float var = sq[0] * (1.f / (float)D_) - mu * mu;
    const float rstd = rsqrtf(var + EPS_LN);
#pragma unroll
    for (int i = 0; i < 4; i++) {
        const int c = t + i * 256;
        out[base + c] = (yv[i] - mu) * rstd * gamma[c] + beta[c];
    }
}

// ------------------------- launch --------------------------------------------
extern "C" void kernel_launch(void* const* d_in, const int* in_sizes, int n_in,
                              void* d_out, int out_size) {
    const float* x     = (const float*)d_in[0];
    const float* Wq    = (const float*)d_in[1];
    const float* Wk    = (const float*)d_in[2];
    const float* Wv    = (const float*)d_in[3];
    const float* Wo    = (const float*)d_in[4];
    const float* bo    = (const float*)d_in[5];
    const float* proj  = (const float*)d_in[6];
    const float* gamma = (const float*)d_in[7];
    const float* beta  = (const float*)d_in[8];
    float* out = (float*)d_out;

    float *pQ, *pK, *pV, *pkf, *pkd, *prm, *pkm, *po2;
    __nv_bfloat16 *pxh, *pxl, *pah, *pal, *pWth, *pWtl;
    __nv_bfloat16 *pqfh, *pqfl, *pkTh, *pkTl, *pvTh, *pvTl, *pcTh, *pcTl;
    cudaGetSymbolAddress((void**)&pQ,   g_Q);
    cudaGetSymbolAddress((void**)&pK,   g_K);
    cudaGetSymbolAddress((void**)&pV,   g_V);
    cudaGetSymbolAddress((void**)&pkf,  g_kf);
    cudaGetSymbolAddress((void**)&pkd,  g_kdiag);
    cudaGetSymbolAddress((void**)&prm,  g_krowmax);
    cudaGetSymbolAddress((void**)&pkm,  g_kmax);
    cudaGetSymbolAddress((void**)&po2,  g_out2);
    cudaGetSymbolAddress((void**)&pxh,  g_xh);
    cudaGetSymbolAddress((void**)&pxl,  g_xl);
    cudaGetSymbolAddress((void**)&pah,  g_ah);
    cudaGetSymbolAddress((void**)&pal,  g_al);
    cudaGetSymbolAddress((void**)&pWth, g_Wth);
    cudaGetSymbolAddress((void**)&pWtl, g_Wtl);
    cudaGetSymbolAddress((void**)&pqfh, g_qfh);
    cudaGetSymbolAddress((void**)&pqfl, g_qfl);
    cudaGetSymbolAddress((void**)&pkTh, g_kTh);
    cudaGetSymbolAddress((void**)&pkTl, g_kTl);
    cudaGetSymbolAddress((void**)&pvTh, g_vTh);
    cudaGetSymbolAddress((void**)&pvTl, g_vTl);
    cudaGetSymbolAddress((void**)&pcTh, g_cTh);
    cudaGetSymbolAddress((void**)&pcTl, g_cTl);

    cudaFuncSetAttribute(gemm_bf16x3, cudaFuncAttributeMaxDynamicSharedMemorySize, GSMEM);
    cudaFuncSetAttribute(feat_kernel<0>, cudaFuncAttributeMaxDynamicSharedMemorySize, FEAT_SMEM);
    cudaFuncSetAttribute(feat_kernel<1>, cudaFuncAttributeMaxDynamicSharedMemorySize, FEAT_SMEM);
    cudaFuncSetAttribute(ctx_mma_kernel, cudaFuncAttributeMaxDynamicSharedMemorySize, CTX_SMEM);
    cudaFuncSetAttribute(attn_mma_kernel, cudaFuncAttributeMaxDynamicSharedMemorySize, AT_SMEM);

    const size_t WSZ = (size_t)D_ * D_;

    // 0. operand prep
    split_x_kernel<<<BN_ * D_ / (256 * 4), 256>>>(x, pxh, pxl);
    splitT_W_kernel<<<dim3(32, 32), dim3(32, 32)>>>(Wq, pWth + 0 * WSZ, pWtl + 0 * WSZ);
    splitT_W_kernel<<<dim3(32, 32), dim3(32, 32)>>>(Wk, pWth + 1 * WSZ, pWtl + 1 * WSZ);
    splitT_W_kernel<<<dim3(32, 32), dim3(32, 32)>>>(Wv, pWth + 2 * WSZ, pWtl + 2 * WSZ);
    splitT_W_kernel<<<dim3(32, 32), dim3(32, 32)>>>(Wo, pWth + 3 * WSZ, pWtl + 3 * WSZ);

    dim3 gemmGrid(D_ / 128, BN_ / 128);

    // 1. QKV projections
    gemm_bf16x3<<<gemmGrid, 256, GSMEM>>>(pxh, pxl, pWth + 0 * WSZ, pWtl + 0 * WSZ, pQ);
    gemm_bf16x3<<<gemmGrid, 256, GSMEM>>>(pxh, pxl, pWth + 1 * WSZ, pWtl + 1 * WSZ, pK);
    gemm_bf16x3<<<gemmGrid, 256, GSMEM>>>(pxh, pxl, pWth + 2 * WSZ, pWtl + 2 * WSZ, pV);

    // 2. FAVOR+ features
    dim3 featGrid(N_ / 64, B_ * H_);
    feat_kernel<0><<<featGrid, 256, FEAT_SMEM>>>(pQ, proj, nullptr, pqfh, pqfl, nullptr, nullptr);
    feat_kernel<1><<<featGrid, 256, FEAT_SMEM>>>(pK, proj, pkf, nullptr, nullptr, pkd, prm);
    kmax_reduce_kernel<<<B_ * H_, 256>>>(prm, pkm);

    // 3. format conversions for MMA attention chain
    kconvT_kernel<<<dim3(MP_ / 32, N_ / 32, B_ * H_), dim3(32, 32)>>>(pkf, pkd, pkm, pkTh, pkTl);
    vconvT_kernel<<<dim3(N_ / 32, B_ * H_), 256>>>(pV, pvTh, pvTl);

    // 4. linear attention via tensor cores
    ctx_mma_kernel<<<dim3(3, B_ * H_), 192, CTX_SMEM>>>(pkTh, pkTl, pvTh, pvTl, pcTh, pcTl);
    attn_mma_kernel<<<dim3(N_ / 128, B_ * H_), 256, AT_SMEM>>>(pqfh, pqfl, pcTh, pcTl, pah, pal);

    // 5. Output projection + residual + LayerNorm
    gemm_bf16x3<<<gemmGrid, 256, GSMEM>>>(pah, pal, pWth + 3 * WSZ, pWtl + 3 * WSZ, po2);
    ln_kernel<<<BN_, 256>>>(x, po2, bo, gamma, beta, out);
}